// round 1
// baseline (speedup 1.0000x reference)
#include <cuda_runtime.h>
#include <math.h>

// Problem constants (fixed by setup_inputs)
#define Bq   2
#define Sq   1024
#define DM   2048
#define NH   16
#define NHKV 4
#define DH   128
#define TOKENS (Bq * Sq)          // 2048
#define NREP (NH / NHKV)          // 4

// Scratch (no allocation allowed -> __device__ globals)
__device__ float g_q [TOKENS * NH   * DH];   // 16 MB
__device__ float g_k [TOKENS * NHKV * DH];   //  4 MB
__device__ float g_v [TOKENS * NHKV * DH];   //  4 MB
__device__ float g_ao[TOKENS * NH   * DH];   // 16 MB

// ---------------------------------------------------------------------------
// SGEMM: C[M,N] = A[M,K] @ W[N,K]^T + bias[N]
// BM=BN=128, BK=16, 256 threads, 8x8 microtile. M,N % 128 == 0, K % 16 == 0.
// ---------------------------------------------------------------------------
__global__ __launch_bounds__(256, 1)
void sgemm_bias_kernel(const float* __restrict__ A,
                       const float* __restrict__ W,
                       const float* __restrict__ bias,
                       float* __restrict__ C,
                       int M, int N, int K)
{
    __shared__ float As[16][132];   // [k][m], padded
    __shared__ float Bs[16][132];   // [k][n], padded

    const int tid  = threadIdx.x;
    const int tRow = tid >> 4;          // 0..15
    const int tCol = tid & 15;          // 0..15
    const int blkM = blockIdx.y * 128;
    const int blkN = blockIdx.x * 128;

    const int ldRow = tid >> 2;         // 0..63
    const int ldCol = (tid & 3) << 2;   // 0,4,8,12

    float acc[8][8];
#pragma unroll
    for (int i = 0; i < 8; i++)
#pragma unroll
        for (int j = 0; j < 8; j++) acc[i][j] = 0.f;

    for (int k0 = 0; k0 < K; k0 += 16) {
        // load A tile (128 x 16) transposed into As[k][m]
#pragma unroll
        for (int r = 0; r < 128; r += 64) {
            float4 t = *(const float4*)&A[(long)(blkM + ldRow + r) * K + k0 + ldCol];
            As[ldCol + 0][ldRow + r] = t.x;
            As[ldCol + 1][ldRow + r] = t.y;
            As[ldCol + 2][ldRow + r] = t.z;
            As[ldCol + 3][ldRow + r] = t.w;
        }
        // load W tile (128 x 16) transposed into Bs[k][n]
#pragma unroll
        for (int r = 0; r < 128; r += 64) {
            float4 t = *(const float4*)&W[(long)(blkN + ldRow + r) * K + k0 + ldCol];
            Bs[ldCol + 0][ldRow + r] = t.x;
            Bs[ldCol + 1][ldRow + r] = t.y;
            Bs[ldCol + 2][ldRow + r] = t.z;
            Bs[ldCol + 3][ldRow + r] = t.w;
        }
        __syncthreads();

#pragma unroll
        for (int kk = 0; kk < 16; kk++) {
            float4 a0 = *(const float4*)&As[kk][tRow * 8];
            float4 a1 = *(const float4*)&As[kk][tRow * 8 + 4];
            float4 b0 = *(const float4*)&Bs[kk][tCol * 8];
            float4 b1 = *(const float4*)&Bs[kk][tCol * 8 + 4];
            float ra[8] = {a0.x, a0.y, a0.z, a0.w, a1.x, a1.y, a1.z, a1.w};
            float rb[8] = {b0.x, b0.y, b0.z, b0.w, b1.x, b1.y, b1.z, b1.w};
#pragma unroll
            for (int i = 0; i < 8; i++)
#pragma unroll
                for (int j = 0; j < 8; j++)
                    acc[i][j] = fmaf(ra[i], rb[j], acc[i][j]);
        }
        __syncthreads();
    }

    // epilogue + bias
    const int cBase = blkN + tCol * 8;
    float bb[8];
#pragma unroll
    for (int j = 0; j < 8; j++) bb[j] = bias[cBase + j];
#pragma unroll
    for (int i = 0; i < 8; i++) {
        long row = blkM + tRow * 8 + i;
        float4 o0 = make_float4(acc[i][0] + bb[0], acc[i][1] + bb[1],
                                acc[i][2] + bb[2], acc[i][3] + bb[3]);
        float4 o1 = make_float4(acc[i][4] + bb[4], acc[i][5] + bb[5],
                                acc[i][6] + bb[6], acc[i][7] + bb[7]);
        *(float4*)&C[row * N + cBase]     = o0;
        *(float4*)&C[row * N + cBase + 4] = o1;
    }
}

// ---------------------------------------------------------------------------
// Fused per-head LayerNorm + RoPE (in place). One warp per 128-elem row.
// Lane l owns elements {l, l+32, l+64, l+96}; rotate-half pairs are intra-lane.
// ---------------------------------------------------------------------------
__global__ __launch_bounds__(128)
void ln_rope_kernel(float* __restrict__ x,
                    const float* __restrict__ g,
                    const float* __restrict__ b,
                    const float* __restrict__ cosp,
                    const float* __restrict__ sinp,
                    int nheads)
{
    const int warp = threadIdx.x >> 5;
    const int lane = threadIdx.x & 31;
    const long row = (long)blockIdx.x * 4 + warp;          // (b*S + s)*nheads + h
    const int  s   = (int)((row / nheads) % Sq);

    float* p = x + row * DH;
    float e0 = p[lane], e1 = p[lane + 32], e2 = p[lane + 64], e3 = p[lane + 96];

    float sum = e0 + e1 + e2 + e3;
#pragma unroll
    for (int o = 16; o > 0; o >>= 1) sum += __shfl_xor_sync(0xffffffff, sum, o);
    float mu = sum * (1.0f / DH);

    float d0 = e0 - mu, d1 = e1 - mu, d2 = e2 - mu, d3 = e3 - mu;
    float vs = d0 * d0 + d1 * d1 + d2 * d2 + d3 * d3;
#pragma unroll
    for (int o = 16; o > 0; o >>= 1) vs += __shfl_xor_sync(0xffffffff, vs, o);
    float inv = rsqrtf(vs * (1.0f / DH) + 1e-5f);

    float y0 = d0 * inv * g[lane]      + b[lane];
    float y1 = d1 * inv * g[lane + 32] + b[lane + 32];
    float y2 = d2 * inv * g[lane + 64] + b[lane + 64];
    float y3 = d3 * inv * g[lane + 96] + b[lane + 96];

    const float* cs = cosp + (long)s * DH;
    const float* sn = sinp + (long)s * DH;
    float c0 = cs[lane], c1 = cs[lane + 32], c2 = cs[lane + 64], c3 = cs[lane + 96];
    float s0 = sn[lane], s1 = sn[lane + 32], s2 = sn[lane + 64], s3 = sn[lane + 96];

    // rotate_half: first half gets -x[i+64]*sin, second half gets +x[i-64]*sin
    p[lane]      = y0 * c0 - y2 * s0;
    p[lane + 32] = y1 * c1 - y3 * s1;
    p[lane + 64] = y2 * c2 + y0 * s2;
    p[lane + 96] = y3 * c3 + y1 * s3;
}

// ---------------------------------------------------------------------------
// Causal GQA attention, online softmax. One warp per query row.
// q layout: [b,s,h,d]  (tokens x NH*DH), k/v layout: [b,s,kh,d].
// ---------------------------------------------------------------------------
__global__ __launch_bounds__(128)
void flash_kernel(const float* __restrict__ q,
                  const float* __restrict__ k,
                  const float* __restrict__ v,
                  float* __restrict__ o)
{
    const int warp = threadIdx.x >> 5;
    const int lane = threadIdx.x & 31;
    const long gw = (long)blockIdx.x * 4 + warp;   // ((b*NH + h)*S + sq)
    const int sq = (int)(gw % Sq);
    const int bh = (int)(gw / Sq);
    const int h  = bh % NH;
    const int b  = bh / NH;
    const int kh = h / NREP;

    const float scale = 0.08838834764831845f;  // 1/sqrt(128)

    const float* qp = q + (((long)(b * Sq + sq)) * NH + h) * DH;
    float4 qv = *(const float4*)(qp + lane * 4);

    const long kvBase = ((long)b * Sq * NHKV + kh) * DH;
    const long kvStride = (long)NHKV * DH;

    float m = -1e30f, l = 0.f;
    float a0 = 0.f, a1 = 0.f, a2 = 0.f, a3 = 0.f;

    for (int sk = 0; sk <= sq; sk++) {
        const float* kp = k + kvBase + (long)sk * kvStride;
        float4 kr = *(const float4*)(kp + lane * 4);
        float d = qv.x * kr.x + qv.y * kr.y + qv.z * kr.z + qv.w * kr.w;
#pragma unroll
        for (int off = 16; off > 0; off >>= 1)
            d += __shfl_xor_sync(0xffffffff, d, off);
        d *= scale;

        float m_new = fmaxf(m, d);
        float corr  = __expf(m - m_new);
        float p     = __expf(d - m_new);
        l = l * corr + p;

        const float* vp = v + kvBase + (long)sk * kvStride;
        float4 vr = *(const float4*)(vp + lane * 4);
        a0 = a0 * corr + p * vr.x;
        a1 = a1 * corr + p * vr.y;
        a2 = a2 * corr + p * vr.z;
        a3 = a3 * corr + p * vr.w;
        m = m_new;
    }

    float invl = 1.0f / l;
    float* op = o + (((long)(b * Sq + sq)) * NH + h) * DH + lane * 4;
    op[0] = a0 * invl;
    op[1] = a1 * invl;
    op[2] = a2 * invl;
    op[3] = a3 * invl;
}

// ---------------------------------------------------------------------------
extern "C" void kernel_launch(void* const* d_in, const int* in_sizes, int n_in,
                              void* d_out, int out_size)
{
    const float* hidden = (const float*)d_in[0];
    const float* cosp   = (const float*)d_in[1];
    const float* sinp   = (const float*)d_in[2];
    const float* Wq     = (const float*)d_in[3];
    const float* bq     = (const float*)d_in[4];
    const float* Wk     = (const float*)d_in[5];
    const float* bk     = (const float*)d_in[6];
    const float* Wv     = (const float*)d_in[7];
    const float* bv     = (const float*)d_in[8];
    const float* Wo     = (const float*)d_in[9];
    const float* bo     = (const float*)d_in[10];
    const float* qn_g   = (const float*)d_in[11];
    const float* qn_b   = (const float*)d_in[12];
    const float* kn_g   = (const float*)d_in[13];
    const float* kn_b   = (const float*)d_in[14];
    float* out = (float*)d_out;

    float *qbuf, *kbuf, *vbuf, *aobuf;
    cudaGetSymbolAddress((void**)&qbuf,  g_q);
    cudaGetSymbolAddress((void**)&kbuf,  g_k);
    cudaGetSymbolAddress((void**)&vbuf,  g_v);
    cudaGetSymbolAddress((void**)&aobuf, g_ao);

    // QKV projections
    {
        dim3 gq(NH * DH / 128, TOKENS / 128);
        sgemm_bias_kernel<<<gq, 256>>>(hidden, Wq, bq, qbuf, TOKENS, NH * DH, DM);
        dim3 gk(NHKV * DH / 128, TOKENS / 128);
        sgemm_bias_kernel<<<gk, 256>>>(hidden, Wk, bk, kbuf, TOKENS, NHKV * DH, DM);
        sgemm_bias_kernel<<<gk, 256>>>(hidden, Wv, bv, vbuf, TOKENS, NHKV * DH, DM);
    }

    // LayerNorm + RoPE (in place) on q and k
    ln_rope_kernel<<<TOKENS * NH   / 4, 128>>>(qbuf, qn_g, qn_b, cosp, sinp, NH);
    ln_rope_kernel<<<TOKENS * NHKV / 4, 128>>>(kbuf, kn_g, kn_b, cosp, sinp, NHKV);

    // causal GQA attention
    flash_kernel<<<Bq * NH * Sq / 4, 128>>>(qbuf, kbuf, vbuf, aobuf);

    // output projection
    {
        dim3 go(DM / 128, TOKENS / 128);
        sgemm_bias_kernel<<<go, 256>>>(aobuf, Wo, bo, out, TOKENS, DM, DM);
    }
}

// round 2
// speedup vs baseline: 1.2560x; 1.2560x over previous
#include <cuda_runtime.h>
#include <cuda_bf16.h>
#include <math.h>
#include <stdint.h>

// Problem constants (fixed by setup_inputs)
#define Bq   2
#define Sq   1024
#define DM   2048
#define NH   16
#define NHKV 4
#define DH   128
#define TOKENS (Bq * Sq)          // 2048
#define NREP (NH / NHKV)          // 4

// Scratch (no allocation allowed -> __device__ globals)
__device__ float g_q [TOKENS * NH   * DH];   // 16 MB
__device__ float g_k [TOKENS * NHKV * DH];   //  4 MB
__device__ float g_v [TOKENS * NHKV * DH];   //  4 MB
__device__ float g_ao[TOKENS * NH   * DH];   // 16 MB

// ---------------------------------------------------------------------------
// Tensor-core GEMM with split-bf16 (3-MMA) fp32 emulation.
// C[M,N] = A[M,K] @ W[N,K]^T + bias[N]
// BM=128, BN=128, BK=32. 256 threads = 8 warps (2 x 4), warp tile 64x32.
// mma.sync.aligned.m16n8k16.row.col.f32.bf16.bf16.f32
// A row-major [M,K] (K contiguous), W row-major [N,K] => B col-major [K,N].
// ---------------------------------------------------------------------------
#define BKP 40   // padded row stride in bf16 elems (80 bytes: 16B aligned, conflict-free ldmatrix)

#define LDM_X4(r0,r1,r2,r3,addr) \
    asm volatile("ldmatrix.sync.aligned.m8n8.x4.shared.b16 {%0,%1,%2,%3}, [%4];" \
                 : "=r"(r0),"=r"(r1),"=r"(r2),"=r"(r3) : "r"(addr))
#define LDM_X2(r0,r1,addr) \
    asm volatile("ldmatrix.sync.aligned.m8n8.x2.shared.b16 {%0,%1}, [%2];" \
                 : "=r"(r0),"=r"(r1) : "r"(addr))
#define MMA16816(c,a0,a1,a2,a3,b0,b1) \
    asm volatile("mma.sync.aligned.m16n8k16.row.col.f32.bf16.bf16.f32 " \
                 "{%0,%1,%2,%3},{%4,%5,%6,%7},{%8,%9},{%0,%1,%2,%3};" \
                 : "+f"(c[0]),"+f"(c[1]),"+f"(c[2]),"+f"(c[3]) \
                 : "r"(a0),"r"(a1),"r"(a2),"r"(a3),"r"(b0),"r"(b1))

__device__ __forceinline__ uint32_t pack_hi2(float x, float y) {
    return ((uint32_t)__bfloat16_as_ushort(__float2bfloat16(y)) << 16) |
            (uint32_t)__bfloat16_as_ushort(__float2bfloat16(x));
}
__device__ __forceinline__ float bf_res(float x) {
    __nv_bfloat16 h = __float2bfloat16(x);
    return x - __bfloat162float(h);
}

__global__ __launch_bounds__(256, 1)
void gemm_tc_kernel(const float* __restrict__ A,
                    const float* __restrict__ W,
                    const float* __restrict__ bias,
                    float* __restrict__ C,
                    int M, int N, int K)
{
    __shared__ __align__(16) __nv_bfloat16 Ah[128 * BKP];
    __shared__ __align__(16) __nv_bfloat16 Al[128 * BKP];
    __shared__ __align__(16) __nv_bfloat16 Bh[128 * BKP];
    __shared__ __align__(16) __nv_bfloat16 Bl[128 * BKP];

    const int tid  = threadIdx.x;
    const int warp = tid >> 5;
    const int lane = tid & 31;
    const int wm   = (warp >> 2) * 64;   // warp M origin in tile
    const int wn   = (warp & 3) * 32;    // warp N origin in tile
    const int g    = lane >> 2;          // group id
    const int tig  = lane & 3;           // thread in group
    const long blkM = (long)blockIdx.y * 128;
    const long blkN = (long)blockIdx.x * 128;

    float acc[4][4][4];
#pragma unroll
    for (int mi = 0; mi < 4; mi++)
#pragma unroll
        for (int ni = 0; ni < 4; ni++)
#pragma unroll
            for (int e = 0; e < 4; e++) acc[mi][ni][e] = 0.f;

    // ldmatrix shared addresses (fixed per thread, advance by kk)
    const int aRow = wm + (lane & 15);
    const int aCol = (lane >> 4) * 8;
    const int bRow = wn + (lane & 7);
    const int bCol = ((lane >> 3) & 1) * 8;

    const uint32_t ahBase = (uint32_t)__cvta_generic_to_shared(Ah);
    const uint32_t alBase = (uint32_t)__cvta_generic_to_shared(Al);
    const uint32_t bhBase = (uint32_t)__cvta_generic_to_shared(Bh);
    const uint32_t blBase = (uint32_t)__cvta_generic_to_shared(Bl);

    for (int k0 = 0; k0 < K; k0 += 32) {
        // ---- load + split-convert A and W tiles (128 x 32 fp32 each) ----
#pragma unroll
        for (int i = 0; i < 4; i++) {
            int u   = tid + i * 256;         // float4 unit id, 8 per row
            int row = u >> 3;
            int col = (u & 7) * 4;
            {
                float4 t = *(const float4*)&A[(blkM + row) * K + k0 + col];
                *(uint32_t*)&Ah[row * BKP + col]     = pack_hi2(t.x, t.y);
                *(uint32_t*)&Ah[row * BKP + col + 2] = pack_hi2(t.z, t.w);
                *(uint32_t*)&Al[row * BKP + col]     = pack_hi2(bf_res(t.x), bf_res(t.y));
                *(uint32_t*)&Al[row * BKP + col + 2] = pack_hi2(bf_res(t.z), bf_res(t.w));
            }
            {
                float4 t = *(const float4*)&W[(blkN + row) * K + k0 + col];
                *(uint32_t*)&Bh[row * BKP + col]     = pack_hi2(t.x, t.y);
                *(uint32_t*)&Bh[row * BKP + col + 2] = pack_hi2(t.z, t.w);
                *(uint32_t*)&Bl[row * BKP + col]     = pack_hi2(bf_res(t.x), bf_res(t.y));
                *(uint32_t*)&Bl[row * BKP + col + 2] = pack_hi2(bf_res(t.z), bf_res(t.w));
            }
        }
        __syncthreads();

        // ---- two k16 steps ----
#pragma unroll
        for (int kk = 0; kk < 32; kk += 16) {
            uint32_t ah[4][4], al[4][4], bh[4][2], bl[4][2];
#pragma unroll
            for (int mi = 0; mi < 4; mi++) {
                uint32_t off = (uint32_t)(((aRow + mi * 16) * BKP + kk + aCol) * 2);
                LDM_X4(ah[mi][0], ah[mi][1], ah[mi][2], ah[mi][3], ahBase + off);
                LDM_X4(al[mi][0], al[mi][1], al[mi][2], al[mi][3], alBase + off);
            }
#pragma unroll
            for (int ni = 0; ni < 4; ni++) {
                uint32_t off = (uint32_t)(((bRow + ni * 8) * BKP + kk + bCol) * 2);
                LDM_X2(bh[ni][0], bh[ni][1], bhBase + off);
                LDM_X2(bl[ni][0], bl[ni][1], blBase + off);
            }
#pragma unroll
            for (int mi = 0; mi < 4; mi++)
#pragma unroll
                for (int ni = 0; ni < 4; ni++) {
                    MMA16816(acc[mi][ni], ah[mi][0], ah[mi][1], ah[mi][2], ah[mi][3],
                             bh[ni][0], bh[ni][1]);
                    MMA16816(acc[mi][ni], ah[mi][0], ah[mi][1], ah[mi][2], ah[mi][3],
                             bl[ni][0], bl[ni][1]);
                    MMA16816(acc[mi][ni], al[mi][0], al[mi][1], al[mi][2], al[mi][3],
                             bh[ni][0], bh[ni][1]);
                }
        }
        __syncthreads();
    }

    // ---- epilogue: bias + store ----
#pragma unroll
    for (int mi = 0; mi < 4; mi++) {
#pragma unroll
        for (int ni = 0; ni < 4; ni++) {
            long col = blkN + wn + ni * 8 + tig * 2;
            float b0 = bias[col], b1 = bias[col + 1];
            long r0 = blkM + wm + mi * 16 + g;
            long r1 = r0 + 8;
            float2 v0 = make_float2(acc[mi][ni][0] + b0, acc[mi][ni][1] + b1);
            float2 v1 = make_float2(acc[mi][ni][2] + b0, acc[mi][ni][3] + b1);
            *(float2*)&C[r0 * N + col] = v0;
            *(float2*)&C[r1 * N + col] = v1;
        }
    }
}

// ---------------------------------------------------------------------------
// Fused per-head LayerNorm + RoPE (in place). One warp per 128-elem row.
// ---------------------------------------------------------------------------
__global__ __launch_bounds__(128)
void ln_rope_kernel(float* __restrict__ x,
                    const float* __restrict__ g,
                    const float* __restrict__ b,
                    const float* __restrict__ cosp,
                    const float* __restrict__ sinp,
                    int nheads)
{
    const int warp = threadIdx.x >> 5;
    const int lane = threadIdx.x & 31;
    const long row = (long)blockIdx.x * 4 + warp;
    const int  s   = (int)((row / nheads) % Sq);

    float* p = x + row * DH;
    float e0 = p[lane], e1 = p[lane + 32], e2 = p[lane + 64], e3 = p[lane + 96];

    float sum = e0 + e1 + e2 + e3;
#pragma unroll
    for (int o = 16; o > 0; o >>= 1) sum += __shfl_xor_sync(0xffffffff, sum, o);
    float mu = sum * (1.0f / DH);

    float d0 = e0 - mu, d1 = e1 - mu, d2 = e2 - mu, d3 = e3 - mu;
    float vs = d0 * d0 + d1 * d1 + d2 * d2 + d3 * d3;
#pragma unroll
    for (int o = 16; o > 0; o >>= 1) vs += __shfl_xor_sync(0xffffffff, vs, o);
    float inv = rsqrtf(vs * (1.0f / DH) + 1e-5f);

    float y0 = d0 * inv * g[lane]      + b[lane];
    float y1 = d1 * inv * g[lane + 32] + b[lane + 32];
    float y2 = d2 * inv * g[lane + 64] + b[lane + 64];
    float y3 = d3 * inv * g[lane + 96] + b[lane + 96];

    const float* cs = cosp + (long)s * DH;
    const float* sn = sinp + (long)s * DH;
    float c0 = cs[lane], c1 = cs[lane + 32], c2 = cs[lane + 64], c3 = cs[lane + 96];
    float s0 = sn[lane], s1 = sn[lane + 32], s2 = sn[lane + 64], s3 = sn[lane + 96];

    p[lane]      = y0 * c0 - y2 * s0;
    p[lane + 32] = y1 * c1 - y3 * s1;
    p[lane + 64] = y2 * c2 + y0 * s2;
    p[lane + 96] = y3 * c3 + y1 * s3;
}

// ---------------------------------------------------------------------------
// Causal GQA attention, online softmax. One warp per query row.
// ---------------------------------------------------------------------------
__global__ __launch_bounds__(128)
void flash_kernel(const float* __restrict__ q,
                  const float* __restrict__ k,
                  const float* __restrict__ v,
                  float* __restrict__ o)
{
    const int warp = threadIdx.x >> 5;
    const int lane = threadIdx.x & 31;
    const long gw = (long)blockIdx.x * 4 + warp;   // ((b*NH + h)*S + sq)
    const int sq = (int)(gw % Sq);
    const int bh = (int)(gw / Sq);
    const int h  = bh % NH;
    const int b  = bh / NH;
    const int kh = h / NREP;

    const float scale = 0.08838834764831845f;  // 1/sqrt(128)

    const float* qp = q + (((long)(b * Sq + sq)) * NH + h) * DH;
    float4 qv = *(const float4*)(qp + lane * 4);

    const long kvBase = ((long)b * Sq * NHKV + kh) * DH;
    const long kvStride = (long)NHKV * DH;

    float m = -1e30f, l = 0.f;
    float a0 = 0.f, a1 = 0.f, a2 = 0.f, a3 = 0.f;

    for (int sk = 0; sk <= sq; sk++) {
        const float* kp = k + kvBase + (long)sk * kvStride;
        float4 kr = *(const float4*)(kp + lane * 4);
        float d = qv.x * kr.x + qv.y * kr.y + qv.z * kr.z + qv.w * kr.w;
#pragma unroll
        for (int off = 16; off > 0; off >>= 1)
            d += __shfl_xor_sync(0xffffffff, d, off);
        d *= scale;

        float m_new = fmaxf(m, d);
        float corr  = __expf(m - m_new);
        float p     = __expf(d - m_new);
        l = l * corr + p;

        const float* vp = v + kvBase + (long)sk * kvStride;
        float4 vr = *(const float4*)(vp + lane * 4);
        a0 = a0 * corr + p * vr.x;
        a1 = a1 * corr + p * vr.y;
        a2 = a2 * corr + p * vr.z;
        a3 = a3 * corr + p * vr.w;
        m = m_new;
    }

    float invl = 1.0f / l;
    float* op = o + (((long)(b * Sq + sq)) * NH + h) * DH + lane * 4;
    op[0] = a0 * invl;
    op[1] = a1 * invl;
    op[2] = a2 * invl;
    op[3] = a3 * invl;
}

// ---------------------------------------------------------------------------
extern "C" void kernel_launch(void* const* d_in, const int* in_sizes, int n_in,
                              void* d_out, int out_size)
{
    const float* hidden = (const float*)d_in[0];
    const float* cosp   = (const float*)d_in[1];
    const float* sinp   = (const float*)d_in[2];
    const float* Wq     = (const float*)d_in[3];
    const float* bq     = (const float*)d_in[4];
    const float* Wk     = (const float*)d_in[5];
    const float* bk     = (const float*)d_in[6];
    const float* Wv     = (const float*)d_in[7];
    const float* bv     = (const float*)d_in[8];
    const float* Wo     = (const float*)d_in[9];
    const float* bo     = (const float*)d_in[10];
    const float* qn_g   = (const float*)d_in[11];
    const float* qn_b   = (const float*)d_in[12];
    const float* kn_g   = (const float*)d_in[13];
    const float* kn_b   = (const float*)d_in[14];
    float* out = (float*)d_out;

    float *qbuf, *kbuf, *vbuf, *aobuf;
    cudaGetSymbolAddress((void**)&qbuf,  g_q);
    cudaGetSymbolAddress((void**)&kbuf,  g_k);
    cudaGetSymbolAddress((void**)&vbuf,  g_v);
    cudaGetSymbolAddress((void**)&aobuf, g_ao);

    // QKV projections (split-bf16 tensor-core GEMMs)
    {
        dim3 gq(NH * DH / 128, TOKENS / 128);
        gemm_tc_kernel<<<gq, 256>>>(hidden, Wq, bq, qbuf, TOKENS, NH * DH, DM);
        dim3 gk(NHKV * DH / 128, TOKENS / 128);
        gemm_tc_kernel<<<gk, 256>>>(hidden, Wk, bk, kbuf, TOKENS, NHKV * DH, DM);
        gemm_tc_kernel<<<gk, 256>>>(hidden, Wv, bv, vbuf, TOKENS, NHKV * DH, DM);
    }

    // LayerNorm + RoPE (in place) on q and k
    ln_rope_kernel<<<TOKENS * NH   / 4, 128>>>(qbuf, qn_g, qn_b, cosp, sinp, NH);
    ln_rope_kernel<<<TOKENS * NHKV / 4, 128>>>(kbuf, kn_g, kn_b, cosp, sinp, NHKV);

    // causal GQA attention
    flash_kernel<<<Bq * NH * Sq / 4, 128>>>(qbuf, kbuf, vbuf, aobuf);

    // output projection
    {
        dim3 go(DM / 128, TOKENS / 128);
        gemm_tc_kernel<<<go, 256>>>(aobuf, Wo, bo, out, TOKENS, DM, DM);
    }
}

// round 4
// speedup vs baseline: 1.7566x; 1.3986x over previous
#include <cuda_runtime.h>
#include <cuda_bf16.h>
#include <math.h>
#include <stdint.h>

// Problem constants (fixed by setup_inputs)
#define Bq   2
#define Sq   1024
#define DM   2048
#define NH   16
#define NHKV 4
#define DH   128
#define TOKENS (Bq * Sq)          // 2048
#define NREP (NH / NHKV)          // 4
#define NQKV 3072                 // fused QKV output width: 2048 q + 512 k + 512 v
#define KOFF 2048
#define VOFF 2560

// ---------------------------------------------------------------------------
// Scratch (__device__ globals; no allocation allowed)
// ---------------------------------------------------------------------------
__device__ __nv_bfloat16 g_hid_h [TOKENS * DM];
__device__ __nv_bfloat16 g_hid_l [TOKENS * DM];
__device__ __nv_bfloat16 g_wqkv_h[NQKV   * DM];
__device__ __nv_bfloat16 g_wqkv_l[NQKV   * DM];
__device__ __nv_bfloat16 g_wo_h  [DM     * DM];
__device__ __nv_bfloat16 g_wo_l  [DM     * DM];
__device__ float         g_bias  [NQKV];
__device__ float         g_qkv   [TOKENS * NQKV];
__device__ __nv_bfloat16 g_ao_h  [TOKENS * DM];
__device__ __nv_bfloat16 g_ao_l  [TOKENS * DM];

// ---------------------------------------------------------------------------
// helpers
// ---------------------------------------------------------------------------
__device__ __forceinline__ uint32_t pack_hi2(float x, float y) {
    return ((uint32_t)__bfloat16_as_ushort(__float2bfloat16(y)) << 16) |
            (uint32_t)__bfloat16_as_ushort(__float2bfloat16(x));
}
__device__ __forceinline__ float bf_res(float x) {
    __nv_bfloat16 h = __float2bfloat16(x);
    return x - __bfloat162float(h);
}

#define LDM_X4(r0,r1,r2,r3,addr) \
    asm volatile("ldmatrix.sync.aligned.m8n8.x4.shared.b16 {%0,%1,%2,%3}, [%4];" \
                 : "=r"(r0),"=r"(r1),"=r"(r2),"=r"(r3) : "r"(addr))
#define LDM_X2(r0,r1,addr) \
    asm volatile("ldmatrix.sync.aligned.m8n8.x2.shared.b16 {%0,%1}, [%2];" \
                 : "=r"(r0),"=r"(r1) : "r"(addr))
#define MMA16816(c,a0,a1,a2,a3,b0,b1) \
    asm volatile("mma.sync.aligned.m16n8k16.row.col.f32.bf16.bf16.f32 " \
                 "{%0,%1,%2,%3},{%4,%5,%6,%7},{%8,%9},{%0,%1,%2,%3};" \
                 : "+f"(c[0]),"+f"(c[1]),"+f"(c[2]),"+f"(c[3]) \
                 : "r"(a0),"r"(a1),"r"(a2),"r"(a3),"r"(b0),"r"(b1))

__device__ __forceinline__ void cp_async16(uint32_t dst, const void* src) {
    asm volatile("cp.async.cg.shared.global [%0], [%1], 16;" :: "r"(dst), "l"(src));
}
#define CP_COMMIT() asm volatile("cp.async.commit_group;")
#define CP_WAIT1()  asm volatile("cp.async.wait_group 1;")
#define CP_WAIT0()  asm volatile("cp.async.wait_group 0;")

// ---------------------------------------------------------------------------
// split: fp32 -> (hi, lo) bf16
// ---------------------------------------------------------------------------
__global__ __launch_bounds__(256)
void split_kernel(const float* __restrict__ src,
                  __nv_bfloat16* __restrict__ hi,
                  __nv_bfloat16* __restrict__ lo, int n4)
{
    int i = blockIdx.x * 256 + threadIdx.x;
    if (i >= n4) return;
    float4 t = ((const float4*)src)[i];
    uint2 h, l;
    h.x = pack_hi2(t.x, t.y);
    h.y = pack_hi2(t.z, t.w);
    l.x = pack_hi2(bf_res(t.x), bf_res(t.y));
    l.y = pack_hi2(bf_res(t.z), bf_res(t.w));
    ((uint2*)hi)[i] = h;
    ((uint2*)lo)[i] = l;
}

__global__ void concat_bias_kernel(const float* bq, const float* bk,
                                   const float* bv, float* dst)
{
    int i = blockIdx.x * 256 + threadIdx.x;
    if (i < 2048)      dst[i] = bq[i];
    else if (i < 2560) dst[i] = bk[i - 2048];
    else if (i < 3072) dst[i] = bv[i - 2560];
}

// ---------------------------------------------------------------------------
// Split-bf16 tensor-core GEMM, cp.async double-buffered.
// C[M,N] = (Ah+Al)[M,K] @ (Bh+Bl)[N,K]^T + bias[N]   (Al*Bl dropped)
// BM=BN=128, BK=32, 256 threads = 8 warps, warp tile 64x32.
// ---------------------------------------------------------------------------
#define BKP 40                       // padded row stride (bf16 elems) = 80B
#define TILE_ELEM (128 * BKP)        // per sub-tile elems
#define TILE_B    (TILE_ELEM * 2)    // bytes
#define STAGE_B   (4 * TILE_B)       // Ah,Al,Bh,Bl

__global__ __launch_bounds__(256, 1)
void gemm_tc2_kernel(const __nv_bfloat16* __restrict__ Agh,
                     const __nv_bfloat16* __restrict__ Agl,
                     const __nv_bfloat16* __restrict__ Bgh,
                     const __nv_bfloat16* __restrict__ Bgl,
                     const float* __restrict__ bias,
                     float* __restrict__ C,
                     int M, int N, int K)
{
    extern __shared__ __nv_bfloat16 sm[];
    const uint32_t smBase = (uint32_t)__cvta_generic_to_shared(sm);

    const int tid  = threadIdx.x;
    const int warp = tid >> 5;
    const int lane = tid & 31;
    const int wm   = (warp >> 2) * 64;
    const int wn   = (warp & 3) * 32;
    const int g    = lane >> 2;
    const int tig  = lane & 3;
    const long blkM = (long)blockIdx.y * 128;
    const long blkN = (long)blockIdx.x * 128;

    float acc[4][4][4];
#pragma unroll
    for (int mi = 0; mi < 4; mi++)
#pragma unroll
        for (int ni = 0; ni < 4; ni++)
#pragma unroll
            for (int e = 0; e < 4; e++) acc[mi][ni][e] = 0.f;

    const int aRow = wm + (lane & 15);
    const int aCol = (lane >> 4) * 8;
    const int bRow = wn + (lane & 7);
    const int bCol = ((lane >> 3) & 1) * 8;

    // stage loader: 8 cp.async x16B per thread
    const int ldRow = tid >> 2;          // 0..63 base rows (x2 halves)
    const int ldCol = (tid & 3) * 8;     // bf16 col within 32

    const int KT = K / 32;

    // prefetch stage 0
    {
        uint32_t st = smBase;
#pragma unroll
        for (int i = 0; i < 2; i++) {
            int row = ldRow + i * 64;
            long ag = (blkM + row) * (long)K + ldCol;
            long bg = (blkN + row) * (long)K + ldCol;
            uint32_t d = st + (uint32_t)(row * BKP + ldCol) * 2;
            cp_async16(d,                 Agh + ag);
            cp_async16(d + TILE_B,        Agl + ag);
            cp_async16(d + 2 * TILE_B,    Bgh + bg);
            cp_async16(d + 3 * TILE_B,    Bgl + bg);
        }
        CP_COMMIT();
    }

    for (int kt = 0; kt < KT; kt++) {
        if (kt + 1 < KT) {
            uint32_t st = smBase + ((kt + 1) & 1) * STAGE_B;
            int k0 = (kt + 1) * 32;
#pragma unroll
            for (int i = 0; i < 2; i++) {
                int row = ldRow + i * 64;
                long ag = (blkM + row) * (long)K + k0 + ldCol;
                long bg = (blkN + row) * (long)K + k0 + ldCol;
                uint32_t d = st + (uint32_t)(row * BKP + ldCol) * 2;
                cp_async16(d,              Agh + ag);
                cp_async16(d + TILE_B,     Agl + ag);
                cp_async16(d + 2 * TILE_B, Bgh + bg);
                cp_async16(d + 3 * TILE_B, Bgl + bg);
            }
            CP_COMMIT();
            CP_WAIT1();
        } else {
            CP_WAIT0();
        }
        __syncthreads();

        const uint32_t st = smBase + (kt & 1) * STAGE_B;
#pragma unroll
        for (int kk = 0; kk < 32; kk += 16) {
            uint32_t ah[4][4], al[4][4], bh[4][2], bl[4][2];
#pragma unroll
            for (int mi = 0; mi < 4; mi++) {
                uint32_t off = (uint32_t)(((aRow + mi * 16) * BKP + kk + aCol) * 2);
                LDM_X4(ah[mi][0], ah[mi][1], ah[mi][2], ah[mi][3], st + off);
                LDM_X4(al[mi][0], al[mi][1], al[mi][2], al[mi][3], st + TILE_B + off);
            }
#pragma unroll
            for (int ni = 0; ni < 4; ni++) {
                uint32_t off = (uint32_t)(((bRow + ni * 8) * BKP + kk + bCol) * 2);
                LDM_X2(bh[ni][0], bh[ni][1], st + 2 * TILE_B + off);
                LDM_X2(bl[ni][0], bl[ni][1], st + 3 * TILE_B + off);
            }
#pragma unroll
            for (int mi = 0; mi < 4; mi++)
#pragma unroll
                for (int ni = 0; ni < 4; ni++) {
                    MMA16816(acc[mi][ni], ah[mi][0], ah[mi][1], ah[mi][2], ah[mi][3],
                             bh[ni][0], bh[ni][1]);
                    MMA16816(acc[mi][ni], ah[mi][0], ah[mi][1], ah[mi][2], ah[mi][3],
                             bl[ni][0], bl[ni][1]);
                    MMA16816(acc[mi][ni], al[mi][0], al[mi][1], al[mi][2], al[mi][3],
                             bh[ni][0], bh[ni][1]);
                }
        }
        __syncthreads();
    }

    // epilogue: bias + store
#pragma unroll
    for (int mi = 0; mi < 4; mi++) {
#pragma unroll
        for (int ni = 0; ni < 4; ni++) {
            long col = blkN + wn + ni * 8 + tig * 2;
            float b0 = bias[col], b1 = bias[col + 1];
            long r0 = blkM + wm + mi * 16 + g;
            long r1 = r0 + 8;
            *(float2*)&C[r0 * N + col] = make_float2(acc[mi][ni][0] + b0, acc[mi][ni][1] + b1);
            *(float2*)&C[r1 * N + col] = make_float2(acc[mi][ni][2] + b0, acc[mi][ni][3] + b1);
        }
    }
}

// ---------------------------------------------------------------------------
// Fused per-head LayerNorm + RoPE (in place, strided rows inside g_qkv).
// One warp per 128-elem head row.
// ---------------------------------------------------------------------------
__global__ __launch_bounds__(128)
void ln_rope_kernel(float* __restrict__ x,        // base of q (or k) block
                    const float* __restrict__ g,
                    const float* __restrict__ b,
                    const float* __restrict__ cosp,
                    const float* __restrict__ sinp,
                    int nheads)
{
    const int warp = threadIdx.x >> 5;
    const int lane = threadIdx.x & 31;
    const long row = (long)blockIdx.x * 4 + warp;
    const long t   = row / nheads;
    const int  h   = (int)(row % nheads);
    const int  s   = (int)(t % Sq);

    float* p = x + t * NQKV + (long)h * DH;
    float e0 = p[lane], e1 = p[lane + 32], e2 = p[lane + 64], e3 = p[lane + 96];

    float sum = e0 + e1 + e2 + e3;
#pragma unroll
    for (int o = 16; o > 0; o >>= 1) sum += __shfl_xor_sync(0xffffffff, sum, o);
    float mu = sum * (1.0f / DH);

    float d0 = e0 - mu, d1 = e1 - mu, d2 = e2 - mu, d3 = e3 - mu;
    float vs = d0 * d0 + d1 * d1 + d2 * d2 + d3 * d3;
#pragma unroll
    for (int o = 16; o > 0; o >>= 1) vs += __shfl_xor_sync(0xffffffff, vs, o);
    float inv = rsqrtf(vs * (1.0f / DH) + 1e-5f);

    float y0 = d0 * inv * g[lane]      + b[lane];
    float y1 = d1 * inv * g[lane + 32] + b[lane + 32];
    float y2 = d2 * inv * g[lane + 64] + b[lane + 64];
    float y3 = d3 * inv * g[lane + 96] + b[lane + 96];

    const float* cs = cosp + (long)s * DH;
    const float* sn = sinp + (long)s * DH;
    float c0 = cs[lane], c1 = cs[lane + 32], c2 = cs[lane + 64], c3 = cs[lane + 96];
    float s0 = sn[lane], s1 = sn[lane + 32], s2 = sn[lane + 64], s3 = sn[lane + 96];

    p[lane]      = y0 * c0 - y2 * s0;
    p[lane + 32] = y1 * c1 - y3 * s1;
    p[lane + 64] = y2 * c2 + y0 * s2;
    p[lane + 96] = y3 * c3 + y1 * s3;
}

// ---------------------------------------------------------------------------
// Causal GQA attention, online softmax. One warp per query row.
// 2-key unroll, warp-uniform rescale branch. Emits (hi,lo) bf16 output.
// ---------------------------------------------------------------------------
__global__ __launch_bounds__(128)
void flash_kernel(const float* __restrict__ qkv,
                  __nv_bfloat16* __restrict__ oh,
                  __nv_bfloat16* __restrict__ ol)
{
    const int warp = threadIdx.x >> 5;
    const int lane = threadIdx.x & 31;
    const long gw = (long)blockIdx.x * 4 + warp;   // ((b*NH + h)*S + sq)
    const int sq = (int)(gw % Sq);
    const int bh = (int)(gw / Sq);
    const int h  = bh % NH;
    const int b  = bh / NH;
    const int kh = h / NREP;

    const float scale = 0.08838834764831845f;  // 1/sqrt(128)

    const float* qp = qkv + ((long)(b * Sq + sq)) * NQKV + (long)h * DH;
    float4 qv = *(const float4*)(qp + lane * 4);
    qv.x *= scale; qv.y *= scale; qv.z *= scale; qv.w *= scale;

    const float* kBase = qkv + (long)b * Sq * NQKV + KOFF + (long)kh * DH + lane * 4;
    const float* vBase = qkv + (long)b * Sq * NQKV + VOFF + (long)kh * DH + lane * 4;

    float m = -1e30f, l = 0.f;
    float a0 = 0.f, a1 = 0.f, a2 = 0.f, a3 = 0.f;

    const int nk = sq + 1;
    const int nfull = nk & ~1;

    for (int sk = 0; sk < nfull; sk += 2) {
        float4 k1 = *(const float4*)(kBase + (long)sk * NQKV);
        float4 k2 = *(const float4*)(kBase + (long)(sk + 1) * NQKV);
        float d1 = qv.x * k1.x + qv.y * k1.y + qv.z * k1.z + qv.w * k1.w;
        float d2 = qv.x * k2.x + qv.y * k2.y + qv.z * k2.z + qv.w * k2.w;
#pragma unroll
        for (int off = 16; off > 0; off >>= 1) {
            d1 += __shfl_xor_sync(0xffffffff, d1, off);
            d2 += __shfl_xor_sync(0xffffffff, d2, off);
        }
        float4 v1 = *(const float4*)(vBase + (long)sk * NQKV);
        float4 v2 = *(const float4*)(vBase + (long)(sk + 1) * NQKV);

        float mx = fmaxf(d1, d2);
        if (mx <= m) {                     // warp-uniform: no rescale
            float p1 = __expf(d1 - m);
            float p2 = __expf(d2 - m);
            l += p1 + p2;
            a0 += p1 * v1.x + p2 * v2.x;
            a1 += p1 * v1.y + p2 * v2.y;
            a2 += p1 * v1.z + p2 * v2.z;
            a3 += p1 * v1.w + p2 * v2.w;
        } else {
            float m_new = mx;
            float corr = __expf(m - m_new);
            float p1 = __expf(d1 - m_new);
            float p2 = __expf(d2 - m_new);
            l = l * corr + p1 + p2;
            a0 = a0 * corr + p1 * v1.x + p2 * v2.x;
            a1 = a1 * corr + p1 * v1.y + p2 * v2.y;
            a2 = a2 * corr + p1 * v1.z + p2 * v2.z;
            a3 = a3 * corr + p1 * v1.w + p2 * v2.w;
            m = m_new;
        }
    }
    if (nfull < nk) {
        int sk = nfull;
        float4 k1 = *(const float4*)(kBase + (long)sk * NQKV);
        float d1 = qv.x * k1.x + qv.y * k1.y + qv.z * k1.z + qv.w * k1.w;
#pragma unroll
        for (int off = 16; off > 0; off >>= 1)
            d1 += __shfl_xor_sync(0xffffffff, d1, off);
        float4 v1 = *(const float4*)(vBase + (long)sk * NQKV);
        if (d1 <= m) {
            float p1 = __expf(d1 - m);
            l += p1;
            a0 += p1 * v1.x; a1 += p1 * v1.y; a2 += p1 * v1.z; a3 += p1 * v1.w;
        } else {
            float corr = __expf(m - d1);
            l = l * corr + 1.0f;
            a0 = a0 * corr + v1.x; a1 = a1 * corr + v1.y;
            a2 = a2 * corr + v1.z; a3 = a3 * corr + v1.w;
            m = d1;
        }
    }

    float invl = 1.0f / l;
    float o0 = a0 * invl, o1 = a1 * invl, o2 = a2 * invl, o3 = a3 * invl;

    long base = (((long)(b * Sq + sq)) * NH + h) * DH + lane * 4;
    uint2 hh, ll;
    hh.x = pack_hi2(o0, o1);
    hh.y = pack_hi2(o2, o3);
    ll.x = pack_hi2(bf_res(o0), bf_res(o1));
    ll.y = pack_hi2(bf_res(o2), bf_res(o3));
    *(uint2*)&oh[base] = hh;
    *(uint2*)&ol[base] = ll;
}

// ---------------------------------------------------------------------------
extern "C" void kernel_launch(void* const* d_in, const int* in_sizes, int n_in,
                              void* d_out, int out_size)
{
    const float* hidden = (const float*)d_in[0];
    const float* cosp   = (const float*)d_in[1];
    const float* sinp   = (const float*)d_in[2];
    const float* Wq     = (const float*)d_in[3];
    const float* bq     = (const float*)d_in[4];
    const float* Wk     = (const float*)d_in[5];
    const float* bk     = (const float*)d_in[6];
    const float* Wv     = (const float*)d_in[7];
    const float* bv     = (const float*)d_in[8];
    const float* Wo     = (const float*)d_in[9];
    const float* bo     = (const float*)d_in[10];
    const float* qn_g   = (const float*)d_in[11];
    const float* qn_b   = (const float*)d_in[12];
    const float* kn_g   = (const float*)d_in[13];
    const float* kn_b   = (const float*)d_in[14];
    float* out = (float*)d_out;

    __nv_bfloat16 *hidh, *hidl, *wqkvh, *wqkvl, *woh, *wol, *aoh, *aol;
    float *biasq, *qkv;
    cudaGetSymbolAddress((void**)&hidh,  g_hid_h);
    cudaGetSymbolAddress((void**)&hidl,  g_hid_l);
    cudaGetSymbolAddress((void**)&wqkvh, g_wqkv_h);
    cudaGetSymbolAddress((void**)&wqkvl, g_wqkv_l);
    cudaGetSymbolAddress((void**)&woh,   g_wo_h);
    cudaGetSymbolAddress((void**)&wol,   g_wo_l);
    cudaGetSymbolAddress((void**)&biasq, g_bias);
    cudaGetSymbolAddress((void**)&qkv,   g_qkv);
    cudaGetSymbolAddress((void**)&aoh,   g_ao_h);
    cudaGetSymbolAddress((void**)&aol,   g_ao_l);

    cudaFuncSetAttribute(gemm_tc2_kernel,
                         cudaFuncAttributeMaxDynamicSharedMemorySize, 2 * STAGE_B);

    // ---- split conversions (fp32 -> hi/lo bf16) ----
    {
        int n4;
        n4 = TOKENS * DM / 4;
        split_kernel<<<(n4 + 255) / 256, 256>>>(hidden, hidh, hidl, n4);
        n4 = 2048 * DM / 4;
        split_kernel<<<(n4 + 255) / 256, 256>>>(Wq, wqkvh, wqkvl, n4);
        n4 = 512 * DM / 4;
        split_kernel<<<(n4 + 255) / 256, 256>>>(Wk, wqkvh + 2048L * DM, wqkvl + 2048L * DM, n4);
        split_kernel<<<(n4 + 255) / 256, 256>>>(Wv, wqkvh + 2560L * DM, wqkvl + 2560L * DM, n4);
        n4 = DM * DM / 4;
        split_kernel<<<(n4 + 255) / 256, 256>>>(Wo, woh, wol, n4);
        concat_bias_kernel<<<12, 256>>>(bq, bk, bv, biasq);
    }

    // ---- fused QKV projection: [2048 x 3072] ----
    {
        dim3 grid(NQKV / 128, TOKENS / 128);
        gemm_tc2_kernel<<<grid, 256, 2 * STAGE_B>>>(hidh, hidl, wqkvh, wqkvl,
                                                    biasq, qkv, TOKENS, NQKV, DM);
    }

    // ---- LayerNorm + RoPE (in place in g_qkv) ----
    ln_rope_kernel<<<TOKENS * NH   / 4, 128>>>(qkv,        qn_g, qn_b, cosp, sinp, NH);
    ln_rope_kernel<<<TOKENS * NHKV / 4, 128>>>(qkv + KOFF, kn_g, kn_b, cosp, sinp, NHKV);

    // ---- causal GQA attention (emits hi/lo bf16) ----
    flash_kernel<<<Bq * NH * Sq / 4, 128>>>(qkv, aoh, aol);

    // ---- output projection ----
    {
        dim3 grid(DM / 128, TOKENS / 128);
        gemm_tc2_kernel<<<grid, 256, 2 * STAGE_B>>>(aoh, aol, woh, wol,
                                                    bo, out, TOKENS, DM, DM);
    }
}

// round 5
// speedup vs baseline: 4.3246x; 2.4619x over previous
#include <cuda_runtime.h>
#include <cuda_bf16.h>
#include <math.h>
#include <stdint.h>

// Problem constants (fixed by setup_inputs)
#define Bq   2
#define Sq   1024
#define DM   2048
#define NH   16
#define NHKV 4
#define DH   128
#define TOKENS (Bq * Sq)          // 2048
#define NREP (NH / NHKV)          // 4
#define NQKV 3072                 // fused QKV output width
#define KOFF 2048
#define VOFF 2560

// ---------------------------------------------------------------------------
// Scratch (__device__ globals; no allocation allowed)
// ---------------------------------------------------------------------------
__device__ __align__(16) __nv_bfloat16 g_hid_h [TOKENS * DM];
__device__ __align__(16) __nv_bfloat16 g_hid_l [TOKENS * DM];
__device__ __align__(16) __nv_bfloat16 g_wqkv_h[NQKV   * DM];
__device__ __align__(16) __nv_bfloat16 g_wqkv_l[NQKV   * DM];
__device__ __align__(16) __nv_bfloat16 g_wo_h  [DM     * DM];
__device__ __align__(16) __nv_bfloat16 g_wo_l  [DM     * DM];
__device__ float         g_bias  [NQKV];
__device__ __align__(16) float g_qkv [TOKENS * NQKV];
// pre-split attention operands
__device__ __align__(16) __nv_bfloat16 g_qh[TOKENS * NH   * DH];
__device__ __align__(16) __nv_bfloat16 g_ql[TOKENS * NH   * DH];
__device__ __align__(16) __nv_bfloat16 g_kh[TOKENS * NHKV * DH];
__device__ __align__(16) __nv_bfloat16 g_kl[TOKENS * NHKV * DH];
__device__ __align__(16) __nv_bfloat16 g_vh[TOKENS * NHKV * DH];
__device__ __align__(16) __nv_bfloat16 g_vl[TOKENS * NHKV * DH];
__device__ __align__(16) __nv_bfloat16 g_ao_h[TOKENS * DM];
__device__ __align__(16) __nv_bfloat16 g_ao_l[TOKENS * DM];

// ---------------------------------------------------------------------------
// helpers
// ---------------------------------------------------------------------------
__device__ __forceinline__ uint32_t pack_hi2(float x, float y) {
    return ((uint32_t)__bfloat16_as_ushort(__float2bfloat16(y)) << 16) |
            (uint32_t)__bfloat16_as_ushort(__float2bfloat16(x));
}
__device__ __forceinline__ float bf_res(float x) {
    __nv_bfloat16 h = __float2bfloat16(x);
    return x - __bfloat162float(h);
}

#define LDM_X4(r0,r1,r2,r3,addr) \
    asm volatile("ldmatrix.sync.aligned.m8n8.x4.shared.b16 {%0,%1,%2,%3}, [%4];" \
                 : "=r"(r0),"=r"(r1),"=r"(r2),"=r"(r3) : "r"(addr))
#define LDM_X2(r0,r1,addr) \
    asm volatile("ldmatrix.sync.aligned.m8n8.x2.shared.b16 {%0,%1}, [%2];" \
                 : "=r"(r0),"=r"(r1) : "r"(addr))
#define LDM_X2T(r0,r1,addr) \
    asm volatile("ldmatrix.sync.aligned.m8n8.x2.trans.shared.b16 {%0,%1}, [%2];" \
                 : "=r"(r0),"=r"(r1) : "r"(addr))
#define MMA16816(c,a0,a1,a2,a3,b0,b1) \
    asm volatile("mma.sync.aligned.m16n8k16.row.col.f32.bf16.bf16.f32 " \
                 "{%0,%1,%2,%3},{%4,%5,%6,%7},{%8,%9},{%0,%1,%2,%3};" \
                 : "+f"(c[0]),"+f"(c[1]),"+f"(c[2]),"+f"(c[3]) \
                 : "r"(a0),"r"(a1),"r"(a2),"r"(a3),"r"(b0),"r"(b1))

__device__ __forceinline__ void cp_async16(uint32_t dst, const void* src) {
    asm volatile("cp.async.cg.shared.global [%0], [%1], 16;" :: "r"(dst), "l"(src));
}
#define CP_COMMIT() asm volatile("cp.async.commit_group;")
#define CP_WAIT1()  asm volatile("cp.async.wait_group 1;")
#define CP_WAIT0()  asm volatile("cp.async.wait_group 0;")

// ---------------------------------------------------------------------------
// split: fp32 -> (hi, lo) bf16
// ---------------------------------------------------------------------------
__global__ __launch_bounds__(256)
void split_kernel(const float* __restrict__ src,
                  __nv_bfloat16* __restrict__ hi,
                  __nv_bfloat16* __restrict__ lo, int n4)
{
    int i = blockIdx.x * 256 + threadIdx.x;
    if (i >= n4) return;
    float4 t = ((const float4*)src)[i];
    uint2 h, l;
    h.x = pack_hi2(t.x, t.y);
    h.y = pack_hi2(t.z, t.w);
    l.x = pack_hi2(bf_res(t.x), bf_res(t.y));
    l.y = pack_hi2(bf_res(t.z), bf_res(t.w));
    ((uint2*)hi)[i] = h;
    ((uint2*)lo)[i] = l;
}

__global__ void concat_bias_kernel(const float* bq, const float* bk,
                                   const float* bv, float* dst)
{
    int i = blockIdx.x * 256 + threadIdx.x;
    if (i < 2048)      dst[i] = bq[i];
    else if (i < 2560) dst[i] = bk[i - 2048];
    else if (i < 3072) dst[i] = bv[i - 2560];
}

// V split + layout permute: g_qkv v-section -> [b][kh][s][d] bf16 hi/lo
__global__ __launch_bounds__(256)
void vsplit_kernel(const float* __restrict__ qkv,
                   __nv_bfloat16* __restrict__ vh,
                   __nv_bfloat16* __restrict__ vl)
{
    int idx = blockIdx.x * 256 + threadIdx.x;    // 262144 total
    int vi = idx * 4;
    int t = vi >> 9;         // token
    int c = vi & 511;        // col within 512
    int kh = c >> 7;
    int d  = c & 127;
    int b = t >> 10, s = t & 1023;
    float4 val = *(const float4*)&qkv[(long)t * NQKV + VOFF + c];
    long o = (((long)(b * NHKV + kh)) * Sq + s) * DH + d;
    uint2 h, l;
    h.x = pack_hi2(val.x, val.y);
    h.y = pack_hi2(val.z, val.w);
    l.x = pack_hi2(bf_res(val.x), bf_res(val.y));
    l.y = pack_hi2(bf_res(val.z), bf_res(val.w));
    *(uint2*)&vh[o] = h;
    *(uint2*)&vl[o] = l;
}

// ---------------------------------------------------------------------------
// Split-bf16 tensor-core GEMM, cp.async double-buffered. (unchanged, verified)
// ---------------------------------------------------------------------------
#define BKP 40
#define TILE_ELEM (128 * BKP)
#define TILE_B    (TILE_ELEM * 2)
#define STAGE_B   (4 * TILE_B)

__global__ __launch_bounds__(256, 1)
void gemm_tc2_kernel(const __nv_bfloat16* __restrict__ Agh,
                     const __nv_bfloat16* __restrict__ Agl,
                     const __nv_bfloat16* __restrict__ Bgh,
                     const __nv_bfloat16* __restrict__ Bgl,
                     const float* __restrict__ bias,
                     float* __restrict__ C,
                     int M, int N, int K)
{
    extern __shared__ __nv_bfloat16 sm[];
    const uint32_t smBase = (uint32_t)__cvta_generic_to_shared(sm);

    const int tid  = threadIdx.x;
    const int warp = tid >> 5;
    const int lane = tid & 31;
    const int wm   = (warp >> 2) * 64;
    const int wn   = (warp & 3) * 32;
    const int g    = lane >> 2;
    const int tig  = lane & 3;
    const long blkM = (long)blockIdx.y * 128;
    const long blkN = (long)blockIdx.x * 128;

    float acc[4][4][4];
#pragma unroll
    for (int mi = 0; mi < 4; mi++)
#pragma unroll
        for (int ni = 0; ni < 4; ni++)
#pragma unroll
            for (int e = 0; e < 4; e++) acc[mi][ni][e] = 0.f;

    const int aRow = wm + (lane & 15);
    const int aCol = (lane >> 4) * 8;
    const int bRow = wn + (lane & 7);
    const int bCol = ((lane >> 3) & 1) * 8;

    const int ldRow = tid >> 2;
    const int ldCol = (tid & 3) * 8;

    const int KT = K / 32;

    {
        uint32_t st = smBase;
#pragma unroll
        for (int i = 0; i < 2; i++) {
            int row = ldRow + i * 64;
            long ag = (blkM + row) * (long)K + ldCol;
            long bg = (blkN + row) * (long)K + ldCol;
            uint32_t d = st + (uint32_t)(row * BKP + ldCol) * 2;
            cp_async16(d,                 Agh + ag);
            cp_async16(d + TILE_B,        Agl + ag);
            cp_async16(d + 2 * TILE_B,    Bgh + bg);
            cp_async16(d + 3 * TILE_B,    Bgl + bg);
        }
        CP_COMMIT();
    }

    for (int kt = 0; kt < KT; kt++) {
        if (kt + 1 < KT) {
            uint32_t st = smBase + ((kt + 1) & 1) * STAGE_B;
            int k0 = (kt + 1) * 32;
#pragma unroll
            for (int i = 0; i < 2; i++) {
                int row = ldRow + i * 64;
                long ag = (blkM + row) * (long)K + k0 + ldCol;
                long bg = (blkN + row) * (long)K + k0 + ldCol;
                uint32_t d = st + (uint32_t)(row * BKP + ldCol) * 2;
                cp_async16(d,              Agh + ag);
                cp_async16(d + TILE_B,     Agl + ag);
                cp_async16(d + 2 * TILE_B, Bgh + bg);
                cp_async16(d + 3 * TILE_B, Bgl + bg);
            }
            CP_COMMIT();
            CP_WAIT1();
        } else {
            CP_WAIT0();
        }
        __syncthreads();

        const uint32_t st = smBase + (kt & 1) * STAGE_B;
#pragma unroll
        for (int kk = 0; kk < 32; kk += 16) {
            uint32_t ah[4][4], al[4][4], bh[4][2], bl[4][2];
#pragma unroll
            for (int mi = 0; mi < 4; mi++) {
                uint32_t off = (uint32_t)(((aRow + mi * 16) * BKP + kk + aCol) * 2);
                LDM_X4(ah[mi][0], ah[mi][1], ah[mi][2], ah[mi][3], st + off);
                LDM_X4(al[mi][0], al[mi][1], al[mi][2], al[mi][3], st + TILE_B + off);
            }
#pragma unroll
            for (int ni = 0; ni < 4; ni++) {
                uint32_t off = (uint32_t)(((bRow + ni * 8) * BKP + kk + bCol) * 2);
                LDM_X2(bh[ni][0], bh[ni][1], st + 2 * TILE_B + off);
                LDM_X2(bl[ni][0], bl[ni][1], st + 3 * TILE_B + off);
            }
#pragma unroll
            for (int mi = 0; mi < 4; mi++)
#pragma unroll
                for (int ni = 0; ni < 4; ni++) {
                    MMA16816(acc[mi][ni], ah[mi][0], ah[mi][1], ah[mi][2], ah[mi][3],
                             bh[ni][0], bh[ni][1]);
                    MMA16816(acc[mi][ni], ah[mi][0], ah[mi][1], ah[mi][2], ah[mi][3],
                             bl[ni][0], bl[ni][1]);
                    MMA16816(acc[mi][ni], al[mi][0], al[mi][1], al[mi][2], al[mi][3],
                             bh[ni][0], bh[ni][1]);
                }
        }
        __syncthreads();
    }

#pragma unroll
    for (int mi = 0; mi < 4; mi++) {
#pragma unroll
        for (int ni = 0; ni < 4; ni++) {
            long col = blkN + wn + ni * 8 + tig * 2;
            float b0 = bias[col], b1 = bias[col + 1];
            long r0 = blkM + wm + mi * 16 + g;
            long r1 = r0 + 8;
            *(float2*)&C[r0 * N + col] = make_float2(acc[mi][ni][0] + b0, acc[mi][ni][1] + b1);
            *(float2*)&C[r1 * N + col] = make_float2(acc[mi][ni][2] + b0, acc[mi][ni][3] + b1);
        }
    }
}

// ---------------------------------------------------------------------------
// Fused LayerNorm + RoPE; emits pre-split, pre-scaled bf16 hi/lo into
// [b][head][s][d] layout. One warp per 128-elem head row.
// ---------------------------------------------------------------------------
__global__ __launch_bounds__(128)
void ln_rope_split_kernel(const float* __restrict__ xbase,   // q or k col block
                          const float* __restrict__ g,
                          const float* __restrict__ b,
                          const float* __restrict__ cosp,
                          const float* __restrict__ sinp,
                          int nheads,
                          __nv_bfloat16* __restrict__ oh,
                          __nv_bfloat16* __restrict__ ol,
                          float prescale)
{
    const int warp = threadIdx.x >> 5;
    const int lane = threadIdx.x & 31;
    const long row = (long)blockIdx.x * 4 + warp;
    const long t   = row / nheads;
    const int  h   = (int)(row % nheads);
    const int  bb  = (int)(t >> 10);
    const int  s   = (int)(t & 1023);

    const float* p = xbase + t * NQKV + (long)h * DH;
    float e0 = p[lane], e1 = p[lane + 32], e2 = p[lane + 64], e3 = p[lane + 96];

    float sum = e0 + e1 + e2 + e3;
#pragma unroll
    for (int o = 16; o > 0; o >>= 1) sum += __shfl_xor_sync(0xffffffff, sum, o);
    float mu = sum * (1.0f / DH);

    float d0 = e0 - mu, d1 = e1 - mu, d2 = e2 - mu, d3 = e3 - mu;
    float vs = d0 * d0 + d1 * d1 + d2 * d2 + d3 * d3;
#pragma unroll
    for (int o = 16; o > 0; o >>= 1) vs += __shfl_xor_sync(0xffffffff, vs, o);
    float inv = rsqrtf(vs * (1.0f / DH) + 1e-5f);

    float y0 = d0 * inv * g[lane]      + b[lane];
    float y1 = d1 * inv * g[lane + 32] + b[lane + 32];
    float y2 = d2 * inv * g[lane + 64] + b[lane + 64];
    float y3 = d3 * inv * g[lane + 96] + b[lane + 96];

    const float* cs = cosp + (long)s * DH;
    const float* sn = sinp + (long)s * DH;
    float c0 = cs[lane], c1 = cs[lane + 32], c2 = cs[lane + 64], c3 = cs[lane + 96];
    float s0 = sn[lane], s1 = sn[lane + 32], s2 = sn[lane + 64], s3 = sn[lane + 96];

    float r0 = (y0 * c0 - y2 * s0) * prescale;
    float r1 = (y1 * c1 - y3 * s1) * prescale;
    float r2 = (y2 * c2 + y0 * s2) * prescale;
    float r3 = (y3 * c3 + y1 * s3) * prescale;

    long off = (((long)(bb * nheads + h)) * Sq + s) * DH;
    __nv_bfloat16 h0 = __float2bfloat16(r0), h1 = __float2bfloat16(r1);
    __nv_bfloat16 h2 = __float2bfloat16(r2), h3 = __float2bfloat16(r3);
    oh[off + lane]      = h0;
    oh[off + lane + 32] = h1;
    oh[off + lane + 64] = h2;
    oh[off + lane + 96] = h3;
    ol[off + lane]      = __float2bfloat16(r0 - __bfloat162float(h0));
    ol[off + lane + 32] = __float2bfloat16(r1 - __bfloat162float(h1));
    ol[off + lane + 64] = __float2bfloat16(r2 - __bfloat162float(h2));
    ol[off + lane + 96] = __float2bfloat16(r3 - __bfloat162float(h3));
}

// ---------------------------------------------------------------------------
// Tensor-core causal flash attention, split-bf16 (3-MMA) for QK^T and PV.
// CTA: (b,h,qtile of 128 rows). 8 warps x m16. K-tile = 64 keys, dbl-buffered.
// ---------------------------------------------------------------------------
#define FROWB 272                 // padded row stride (136 bf16)
#define FQH 0
#define FQL 34816
#define FKH(buf) (69632  + (buf) * 17408)
#define FKL(buf) (104448 + (buf) * 17408)
#define FVH(buf) (139264 + (buf) * 17408)
#define FVL(buf) (174080 + (buf) * 17408)
#define FSMEM 208896

__global__ __launch_bounds__(256, 1)
void flash_tc_kernel(const __nv_bfloat16* __restrict__ qh,
                     const __nv_bfloat16* __restrict__ ql,
                     const __nv_bfloat16* __restrict__ kh,
                     const __nv_bfloat16* __restrict__ kl,
                     const __nv_bfloat16* __restrict__ vh,
                     const __nv_bfloat16* __restrict__ vl,
                     __nv_bfloat16* __restrict__ oh,
                     __nv_bfloat16* __restrict__ ol)
{
    extern __shared__ char fsm[];
    const uint32_t sb = (uint32_t)__cvta_generic_to_shared(fsm);

    const int tid  = threadIdx.x;
    const int warp = tid >> 5;
    const int lane = tid & 31;
    const int g    = lane >> 2;
    const int tig  = lane & 3;

    const int bh = blockIdx.x & 31;
    const int qt = 7 - (blockIdx.x >> 5);      // large tiles scheduled first
    const int b  = bh >> 4;
    const int h  = bh & 15;
    const int khd = h >> 2;                    // kv head

    const __nv_bfloat16* Qhg = qh + (((long)(b * NH + h)) * Sq + (long)qt * 128) * DH;
    const __nv_bfloat16* Qlg = ql + (((long)(b * NH + h)) * Sq + (long)qt * 128) * DH;
    const __nv_bfloat16* Khg = kh + ((long)(b * NHKV + khd)) * Sq * DH;
    const __nv_bfloat16* Klg = kl + ((long)(b * NHKV + khd)) * Sq * DH;
    const __nv_bfloat16* Vhg = vh + ((long)(b * NHKV + khd)) * Sq * DH;
    const __nv_bfloat16* Vlg = vl + ((long)(b * NHKV + khd)) * Sq * DH;

    // ---- load Q tile (128 x 128, hi+lo) ----
#pragma unroll
    for (int i = 0; i < 8; i++) {
        int idx = tid + i * 256;
        int row = idx >> 4, cg = idx & 15;
        uint32_t doff = (uint32_t)(row * FROWB + cg * 16);
        cp_async16(sb + FQH + doff, Qhg + row * DH + cg * 8);
        cp_async16(sb + FQL + doff, Qlg + row * DH + cg * 8);
    }
    CP_COMMIT();

    // ---- prefetch KV tile 0 ----
    {
#pragma unroll
        for (int i = 0; i < 4; i++) {
            int idx = tid + i * 256;
            int row = idx >> 4, cg = idx & 15;
            uint32_t doff = (uint32_t)(row * FROWB + cg * 16);
            long soff = (long)row * DH + cg * 8;
            cp_async16(sb + FKH(0) + doff, Khg + soff);
            cp_async16(sb + FKL(0) + doff, Klg + soff);
            cp_async16(sb + FVH(0) + doff, Vhg + soff);
            cp_async16(sb + FVL(0) + doff, Vlg + soff);
        }
        CP_COMMIT();
    }

    float o[16][4];
#pragma unroll
    for (int nd = 0; nd < 16; nd++)
#pragma unroll
        for (int e = 0; e < 4; e++) o[nd][e] = 0.f;
    float m0 = -1e30f, m1 = -1e30f, l0 = 0.f, l1 = 0.f;

    const int row0 = qt * 128 + warp * 16 + g;
    const int row1 = row0 + 8;

    // frag addressing
    const uint32_t qhA = sb + FQH + (uint32_t)((warp * 16 + (lane & 15)) * FROWB + (lane >> 4) * 16);
    const uint32_t qlA = qhA + (FQL - FQH);
    const uint32_t kRowOff = (uint32_t)((lane & 7) * FROWB + ((lane >> 3) & 1) * 16);
    const uint32_t vRowOff = (uint32_t)((lane & 15) * FROWB);

    const int nkt = 2 * qt + 2;
    for (int kt = 0; kt < nkt; kt++) {
        const int buf = kt & 1;
        if (kt + 1 < nkt) {
            const int pb = buf ^ 1;
            const long koff = (long)(kt + 1) * 64 * DH;
#pragma unroll
            for (int i = 0; i < 4; i++) {
                int idx = tid + i * 256;
                int row = idx >> 4, cg = idx & 15;
                uint32_t doff = (uint32_t)(row * FROWB + cg * 16);
                long soff = koff + (long)row * DH + cg * 8;
                cp_async16(sb + FKH(pb) + doff, Khg + soff);
                cp_async16(sb + FKL(pb) + doff, Klg + soff);
                cp_async16(sb + FVH(pb) + doff, Vhg + soff);
                cp_async16(sb + FVL(pb) + doff, Vlg + soff);
            }
            CP_COMMIT();
            CP_WAIT1();
        } else {
            CP_WAIT0();
        }
        __syncthreads();

        // ---- S = Q K^T (split 3-MMA), 8 n8 frags ----
        float s[8][4];
#pragma unroll
        for (int j = 0; j < 8; j++)
#pragma unroll
            for (int e = 0; e < 4; e++) s[j][e] = 0.f;

#pragma unroll
        for (int ks = 0; ks < 8; ks++) {
            uint32_t qh0, qh1, qh2, qh3, ql0, ql1, ql2, ql3;
            LDM_X4(qh0, qh1, qh2, qh3, qhA + ks * 32);
            LDM_X4(ql0, ql1, ql2, ql3, qlA + ks * 32);
            const uint32_t khB = sb + FKH(buf) + kRowOff + ks * 32;
            const uint32_t klB = sb + FKL(buf) + kRowOff + ks * 32;
#pragma unroll
            for (int j = 0; j < 8; j++) {
                uint32_t kb0, kb1, kc0, kc1;
                LDM_X2(kb0, kb1, khB + j * 8 * FROWB);
                LDM_X2(kc0, kc1, klB + j * 8 * FROWB);
                MMA16816(s[j], qh0, qh1, qh2, qh3, kb0, kb1);
                MMA16816(s[j], qh0, qh1, qh2, qh3, kc0, kc1);
                MMA16816(s[j], ql0, ql1, ql2, ql3, kb0, kb1);
            }
        }

        // ---- causal mask (only tiles crossing the diagonal) ----
        if (kt >= 2 * qt) {
#pragma unroll
            for (int j = 0; j < 8; j++) {
                int c = kt * 64 + j * 8 + 2 * tig;
                if (c     > row0) s[j][0] = -1e30f;
                if (c + 1 > row0) s[j][1] = -1e30f;
                if (c     > row1) s[j][2] = -1e30f;
                if (c + 1 > row1) s[j][3] = -1e30f;
            }
        }

        // ---- online softmax ----
        float rm0 = -1e30f, rm1 = -1e30f;
#pragma unroll
        for (int j = 0; j < 8; j++) {
            rm0 = fmaxf(rm0, fmaxf(s[j][0], s[j][1]));
            rm1 = fmaxf(rm1, fmaxf(s[j][2], s[j][3]));
        }
        rm0 = fmaxf(rm0, __shfl_xor_sync(0xffffffff, rm0, 1));
        rm0 = fmaxf(rm0, __shfl_xor_sync(0xffffffff, rm0, 2));
        rm1 = fmaxf(rm1, __shfl_xor_sync(0xffffffff, rm1, 1));
        rm1 = fmaxf(rm1, __shfl_xor_sync(0xffffffff, rm1, 2));

        float m0n = fmaxf(m0, rm0), m1n = fmaxf(m1, rm1);
        float corr0 = __expf(m0 - m0n), corr1 = __expf(m1 - m1n);
        l0 *= corr0; l1 *= corr1;
#pragma unroll
        for (int nd = 0; nd < 16; nd++) {
            o[nd][0] *= corr0; o[nd][1] *= corr0;
            o[nd][2] *= corr1; o[nd][3] *= corr1;
        }
#pragma unroll
        for (int j = 0; j < 8; j++) {
            s[j][0] = __expf(s[j][0] - m0n);
            s[j][1] = __expf(s[j][1] - m0n);
            s[j][2] = __expf(s[j][2] - m1n);
            s[j][3] = __expf(s[j][3] - m1n);
            l0 += s[j][0] + s[j][1];
            l1 += s[j][2] + s[j][3];
        }
        m0 = m0n; m1 = m1n;

        // ---- O += P V (split 3-MMA). A-frags built from S C-frags. ----
#pragma unroll
        for (int kj = 0; kj < 4; kj++) {
            const int j0 = 2 * kj, j1 = 2 * kj + 1;
            uint32_t ah0 = pack_hi2(s[j0][0], s[j0][1]);
            uint32_t ah1 = pack_hi2(s[j0][2], s[j0][3]);
            uint32_t ah2 = pack_hi2(s[j1][0], s[j1][1]);
            uint32_t ah3 = pack_hi2(s[j1][2], s[j1][3]);
            uint32_t al0 = pack_hi2(bf_res(s[j0][0]), bf_res(s[j0][1]));
            uint32_t al1 = pack_hi2(bf_res(s[j0][2]), bf_res(s[j0][3]));
            uint32_t al2 = pack_hi2(bf_res(s[j1][0]), bf_res(s[j1][1]));
            uint32_t al3 = pack_hi2(bf_res(s[j1][2]), bf_res(s[j1][3]));
            const uint32_t vhB = sb + FVH(buf) + vRowOff + kj * 16 * FROWB;
            const uint32_t vlB = sb + FVL(buf) + vRowOff + kj * 16 * FROWB;
#pragma unroll
            for (int nd = 0; nd < 16; nd++) {
                uint32_t vb0, vb1, vc0, vc1;
                LDM_X2T(vb0, vb1, vhB + nd * 16);
                LDM_X2T(vc0, vc1, vlB + nd * 16);
                MMA16816(o[nd], ah0, ah1, ah2, ah3, vb0, vb1);
                MMA16816(o[nd], ah0, ah1, ah2, ah3, vc0, vc1);
                MMA16816(o[nd], al0, al1, al2, al3, vb0, vb1);
            }
        }
        __syncthreads();
    }

    // ---- finalize: l reduce, normalize, store hi/lo bf16 ----
    l0 += __shfl_xor_sync(0xffffffff, l0, 1);
    l0 += __shfl_xor_sync(0xffffffff, l0, 2);
    l1 += __shfl_xor_sync(0xffffffff, l1, 1);
    l1 += __shfl_xor_sync(0xffffffff, l1, 2);
    float inv0 = 1.0f / l0, inv1 = 1.0f / l1;

    const long tok0 = (long)b * Sq + row0 - 0;       // row0 includes qt*128
    long base0 = (tok0) * (long)DM + h * DH + 2 * tig;
    long base1 = base0 + 8L * DM;
#pragma unroll
    for (int nd = 0; nd < 16; nd++) {
        float x0 = o[nd][0] * inv0, x1 = o[nd][1] * inv0;
        float x2 = o[nd][2] * inv1, x3 = o[nd][3] * inv1;
        long a0 = base0 + nd * 8;
        long a1 = base1 + nd * 8;
        *(uint32_t*)&oh[a0] = pack_hi2(x0, x1);
        *(uint32_t*)&ol[a0] = pack_hi2(bf_res(x0), bf_res(x1));
        *(uint32_t*)&oh[a1] = pack_hi2(x2, x3);
        *(uint32_t*)&ol[a1] = pack_hi2(bf_res(x2), bf_res(x3));
    }
}

// ---------------------------------------------------------------------------
extern "C" void kernel_launch(void* const* d_in, const int* in_sizes, int n_in,
                              void* d_out, int out_size)
{
    const float* hidden = (const float*)d_in[0];
    const float* cosp   = (const float*)d_in[1];
    const float* sinp   = (const float*)d_in[2];
    const float* Wq     = (const float*)d_in[3];
    const float* bq     = (const float*)d_in[4];
    const float* Wk     = (const float*)d_in[5];
    const float* bk     = (const float*)d_in[6];
    const float* Wv     = (const float*)d_in[7];
    const float* bv     = (const float*)d_in[8];
    const float* Wo     = (const float*)d_in[9];
    const float* bo     = (const float*)d_in[10];
    const float* qn_g   = (const float*)d_in[11];
    const float* qn_b   = (const float*)d_in[12];
    const float* kn_g   = (const float*)d_in[13];
    const float* kn_b   = (const float*)d_in[14];
    float* out = (float*)d_out;

    __nv_bfloat16 *hidh, *hidl, *wqkvh, *wqkvl, *woh, *wol, *aoh, *aol;
    __nv_bfloat16 *qhb, *qlb, *khb, *klb, *vhb, *vlb;
    float *biasq, *qkv;
    cudaGetSymbolAddress((void**)&hidh,  g_hid_h);
    cudaGetSymbolAddress((void**)&hidl,  g_hid_l);
    cudaGetSymbolAddress((void**)&wqkvh, g_wqkv_h);
    cudaGetSymbolAddress((void**)&wqkvl, g_wqkv_l);
    cudaGetSymbolAddress((void**)&woh,   g_wo_h);
    cudaGetSymbolAddress((void**)&wol,   g_wo_l);
    cudaGetSymbolAddress((void**)&biasq, g_bias);
    cudaGetSymbolAddress((void**)&qkv,   g_qkv);
    cudaGetSymbolAddress((void**)&aoh,   g_ao_h);
    cudaGetSymbolAddress((void**)&aol,   g_ao_l);
    cudaGetSymbolAddress((void**)&qhb,   g_qh);
    cudaGetSymbolAddress((void**)&qlb,   g_ql);
    cudaGetSymbolAddress((void**)&khb,   g_kh);
    cudaGetSymbolAddress((void**)&klb,   g_kl);
    cudaGetSymbolAddress((void**)&vhb,   g_vh);
    cudaGetSymbolAddress((void**)&vlb,   g_vl);

    cudaFuncSetAttribute(gemm_tc2_kernel,
                         cudaFuncAttributeMaxDynamicSharedMemorySize, 2 * STAGE_B);
    cudaFuncSetAttribute(flash_tc_kernel,
                         cudaFuncAttributeMaxDynamicSharedMemorySize, FSMEM);

    // ---- split conversions ----
    {
        int n4;
        n4 = TOKENS * DM / 4;
        split_kernel<<<(n4 + 255) / 256, 256>>>(hidden, hidh, hidl, n4);
        n4 = 2048 * DM / 4;
        split_kernel<<<(n4 + 255) / 256, 256>>>(Wq, wqkvh, wqkvl, n4);
        n4 = 512 * DM / 4;
        split_kernel<<<(n4 + 255) / 256, 256>>>(Wk, wqkvh + 2048L * DM, wqkvl + 2048L * DM, n4);
        split_kernel<<<(n4 + 255) / 256, 256>>>(Wv, wqkvh + 2560L * DM, wqkvl + 2560L * DM, n4);
        n4 = DM * DM / 4;
        split_kernel<<<(n4 + 255) / 256, 256>>>(Wo, woh, wol, n4);
        concat_bias_kernel<<<12, 256>>>(bq, bk, bv, biasq);
    }

    // ---- fused QKV projection ----
    {
        dim3 grid(NQKV / 128, TOKENS / 128);
        gemm_tc2_kernel<<<grid, 256, 2 * STAGE_B>>>(hidh, hidl, wqkvh, wqkvl,
                                                    biasq, qkv, TOKENS, NQKV, DM);
    }

    // ---- LN + RoPE -> pre-split bf16 (q pre-scaled by 1/sqrt(Dh)) ----
    const float scale = 0.08838834764831845f;
    ln_rope_split_kernel<<<TOKENS * NH   / 4, 128>>>(qkv,        qn_g, qn_b, cosp, sinp,
                                                     NH,   qhb, qlb, scale);
    ln_rope_split_kernel<<<TOKENS * NHKV / 4, 128>>>(qkv + KOFF, kn_g, kn_b, cosp, sinp,
                                                     NHKV, khb, klb, 1.0f);
    vsplit_kernel<<<TOKENS * NHKV * DH / 4 / 256, 256>>>(qkv, vhb, vlb);

    // ---- tensor-core causal flash attention ----
    flash_tc_kernel<<<256, 256, FSMEM>>>(qhb, qlb, khb, klb, vhb, vlb, aoh, aol);

    // ---- output projection ----
    {
        dim3 grid(DM / 128, TOKENS / 128);
        gemm_tc2_kernel<<<grid, 256, 2 * STAGE_B>>>(aoh, aol, woh, wol,
                                                    bo, out, TOKENS, DM, DM);
    }
}

// round 7
// speedup vs baseline: 8.4163x; 1.9461x over previous
#include <cuda_runtime.h>
#include <cuda_bf16.h>
#include <cuda_fp16.h>
#include <math.h>
#include <stdint.h>

// Problem constants (fixed by setup_inputs)
#define Bq   2
#define Sq   1024
#define DM   2048
#define NH   16
#define NHKV 4
#define DH   128
#define TOKENS (Bq * Sq)          // 2048
#define NREP (NH / NHKV)          // 4
#define NQKV 3072                 // fused QKV output width
#define KOFF 2048
#define VOFF 2560

// ---------------------------------------------------------------------------
// Scratch (__device__ globals; no allocation allowed)
// ---------------------------------------------------------------------------
__device__ __align__(16) __half g_hid16 [TOKENS * DM];
__device__ __align__(16) __half g_wqkv16[NQKV   * DM];
__device__ __align__(16) __half g_wo16  [DM     * DM];
__device__ float               g_bias   [NQKV];
__device__ __align__(16) float g_qkv    [TOKENS * NQKV];
// pre-split attention operands (bf16 hi/lo, flash stays compensated)
__device__ __align__(16) __nv_bfloat16 g_qh[TOKENS * NH   * DH];
__device__ __align__(16) __nv_bfloat16 g_ql[TOKENS * NH   * DH];
__device__ __align__(16) __nv_bfloat16 g_kh[TOKENS * NHKV * DH];
__device__ __align__(16) __nv_bfloat16 g_kl[TOKENS * NHKV * DH];
__device__ __align__(16) __nv_bfloat16 g_vh[TOKENS * NHKV * DH];
__device__ __align__(16) __nv_bfloat16 g_vl[TOKENS * NHKV * DH];
__device__ __align__(16) __half g_ao16 [TOKENS * DM];

// ---------------------------------------------------------------------------
// helpers
// ---------------------------------------------------------------------------
__device__ __forceinline__ uint32_t pack_hi2(float x, float y) {
    return ((uint32_t)__bfloat16_as_ushort(__float2bfloat16(y)) << 16) |
            (uint32_t)__bfloat16_as_ushort(__float2bfloat16(x));
}
__device__ __forceinline__ float bf_res(float x) {
    __nv_bfloat16 h = __float2bfloat16(x);
    return x - __bfloat162float(h);
}
__device__ __forceinline__ uint32_t pack_half2f(float x, float y) {
    __half2 h = __floats2half2_rn(x, y);
    return *(uint32_t*)&h;
}

#define LDM_X4(r0,r1,r2,r3,addr) \
    asm volatile("ldmatrix.sync.aligned.m8n8.x4.shared.b16 {%0,%1,%2,%3}, [%4];" \
                 : "=r"(r0),"=r"(r1),"=r"(r2),"=r"(r3) : "r"(addr))
#define LDM_X2(r0,r1,addr) \
    asm volatile("ldmatrix.sync.aligned.m8n8.x2.shared.b16 {%0,%1}, [%2];" \
                 : "=r"(r0),"=r"(r1) : "r"(addr))
#define LDM_X2T(r0,r1,addr) \
    asm volatile("ldmatrix.sync.aligned.m8n8.x2.trans.shared.b16 {%0,%1}, [%2];" \
                 : "=r"(r0),"=r"(r1) : "r"(addr))
#define MMA_BF16(c,a0,a1,a2,a3,b0,b1) \
    asm volatile("mma.sync.aligned.m16n8k16.row.col.f32.bf16.bf16.f32 " \
                 "{%0,%1,%2,%3},{%4,%5,%6,%7},{%8,%9},{%0,%1,%2,%3};" \
                 : "+f"(c[0]),"+f"(c[1]),"+f"(c[2]),"+f"(c[3]) \
                 : "r"(a0),"r"(a1),"r"(a2),"r"(a3),"r"(b0),"r"(b1))
#define MMA_F16(c,a0,a1,a2,a3,b0,b1) \
    asm volatile("mma.sync.aligned.m16n8k16.row.col.f32.f16.f16.f32 " \
                 "{%0,%1,%2,%3},{%4,%5,%6,%7},{%8,%9},{%0,%1,%2,%3};" \
                 : "+f"(c[0]),"+f"(c[1]),"+f"(c[2]),"+f"(c[3]) \
                 : "r"(a0),"r"(a1),"r"(a2),"r"(a3),"r"(b0),"r"(b1))

__device__ __forceinline__ void cp_async16(uint32_t dst, const void* src) {
    asm volatile("cp.async.cg.shared.global [%0], [%1], 16;" :: "r"(dst), "l"(src));
}
#define CP_COMMIT() asm volatile("cp.async.commit_group;")
#define CP_WAIT1()  asm volatile("cp.async.wait_group 1;")
#define CP_WAIT0()  asm volatile("cp.async.wait_group 0;")

// ---------------------------------------------------------------------------
// convert: fp32 -> fp16
// ---------------------------------------------------------------------------
__global__ __launch_bounds__(256)
void to_half_kernel(const float* __restrict__ src,
                    __half* __restrict__ dst, int n4)
{
    int i = blockIdx.x * 256 + threadIdx.x;
    if (i >= n4) return;
    float4 t = ((const float4*)src)[i];
    uint2 h;
    h.x = pack_half2f(t.x, t.y);
    h.y = pack_half2f(t.z, t.w);
    ((uint2*)dst)[i] = h;
}

__global__ void concat_bias_kernel(const float* bq, const float* bk,
                                   const float* bv, float* dst)
{
    int i = blockIdx.x * 256 + threadIdx.x;
    if (i < 2048)      dst[i] = bq[i];
    else if (i < 2560) dst[i] = bk[i - 2048];
    else if (i < 3072) dst[i] = bv[i - 2560];
}

// V split + layout permute: g_qkv v-section -> [b][kh][s][d] bf16 hi/lo
__global__ __launch_bounds__(256)
void vsplit_kernel(const float* __restrict__ qkv,
                   __nv_bfloat16* __restrict__ vh,
                   __nv_bfloat16* __restrict__ vl)
{
    int idx = blockIdx.x * 256 + threadIdx.x;    // 262144 total
    int vi = idx * 4;
    int t = vi >> 9;
    int c = vi & 511;
    int kh = c >> 7;
    int d  = c & 127;
    int b = t >> 10, s = t & 1023;
    float4 val = *(const float4*)&qkv[(long)t * NQKV + VOFF + c];
    long o = (((long)(b * NHKV + kh)) * Sq + s) * DH + d;
    uint2 h, l;
    h.x = pack_hi2(val.x, val.y);
    h.y = pack_hi2(val.z, val.w);
    l.x = pack_hi2(bf_res(val.x), bf_res(val.y));
    l.y = pack_hi2(bf_res(val.z), bf_res(val.w));
    *(uint2*)&vh[o] = h;
    *(uint2*)&vl[o] = l;
}

// ---------------------------------------------------------------------------
// Single-pass fp16 tensor-core GEMM, cp.async double-buffered.
// C[M,N] = A[M,K] @ W[N,K]^T + bias[N]
// BM=BN=128, BK=32, 256 threads = 8 warps, warp tile 64x32.
// ---------------------------------------------------------------------------
#define BKP 40                        // padded row stride (halfs) = 80B
#define TILE16_B (128 * BKP * 2)      // 10240 bytes per tile
#define STAGE16_B (2 * TILE16_B)      // A + B

__global__ __launch_bounds__(256)
void gemm_f16_kernel(const __half* __restrict__ Ag,
                     const __half* __restrict__ Bg,
                     const float* __restrict__ bias,
                     float* __restrict__ C,
                     int M, int N, int K)
{
    extern __shared__ __half sm16[];
    const uint32_t smBase = (uint32_t)__cvta_generic_to_shared(sm16);

    const int tid  = threadIdx.x;
    const int warp = tid >> 5;
    const int lane = tid & 31;
    const int wm   = (warp >> 2) * 64;
    const int wn   = (warp & 3) * 32;
    const int g    = lane >> 2;
    const int tig  = lane & 3;
    const long blkM = (long)blockIdx.y * 128;
    const long blkN = (long)blockIdx.x * 128;

    float acc[4][4][4];
#pragma unroll
    for (int mi = 0; mi < 4; mi++)
#pragma unroll
        for (int ni = 0; ni < 4; ni++)
#pragma unroll
            for (int e = 0; e < 4; e++) acc[mi][ni][e] = 0.f;

    const int aRow = wm + (lane & 15);
    const int aCol = (lane >> 4) * 8;
    const int bRow = wn + (lane & 7);
    const int bCol = ((lane >> 3) & 1) * 8;

    const int KT = K / 32;

    // loader mapping: 512 16B-chunks per tile, 2 per thread
    // chunk c: row = c>>2, col = (c&3)*8
    {
        uint32_t st = smBase;
#pragma unroll
        for (int i = 0; i < 2; i++) {
            int c = tid + i * 256;
            int row = c >> 2, col = (c & 3) * 8;
            uint32_t d = st + (uint32_t)(row * BKP + col) * 2;
            cp_async16(d,            Ag + (blkM + row) * (long)K + col);
            cp_async16(d + TILE16_B, Bg + (blkN + row) * (long)K + col);
        }
        CP_COMMIT();
    }

    for (int kt = 0; kt < KT; kt++) {
        if (kt + 1 < KT) {
            uint32_t st = smBase + ((kt + 1) & 1) * STAGE16_B;
            int k0 = (kt + 1) * 32;
#pragma unroll
            for (int i = 0; i < 2; i++) {
                int c = tid + i * 256;
                int row = c >> 2, col = (c & 3) * 8;
                uint32_t d = st + (uint32_t)(row * BKP + col) * 2;
                cp_async16(d,            Ag + (blkM + row) * (long)K + k0 + col);
                cp_async16(d + TILE16_B, Bg + (blkN + row) * (long)K + k0 + col);
            }
            CP_COMMIT();
            CP_WAIT1();
        } else {
            CP_WAIT0();
        }
        __syncthreads();

        const uint32_t st = smBase + (kt & 1) * STAGE16_B;
#pragma unroll
        for (int kk = 0; kk < 32; kk += 16) {
            uint32_t a[4][4], b[4][2];
#pragma unroll
            for (int mi = 0; mi < 4; mi++) {
                uint32_t off = (uint32_t)(((aRow + mi * 16) * BKP + kk + aCol) * 2);
                LDM_X4(a[mi][0], a[mi][1], a[mi][2], a[mi][3], st + off);
            }
#pragma unroll
            for (int ni = 0; ni < 4; ni++) {
                uint32_t off = (uint32_t)(((bRow + ni * 8) * BKP + kk + bCol) * 2);
                LDM_X2(b[ni][0], b[ni][1], st + TILE16_B + off);
            }
#pragma unroll
            for (int mi = 0; mi < 4; mi++)
#pragma unroll
                for (int ni = 0; ni < 4; ni++)
                    MMA_F16(acc[mi][ni], a[mi][0], a[mi][1], a[mi][2], a[mi][3],
                            b[ni][0], b[ni][1]);
        }
        __syncthreads();
    }

#pragma unroll
    for (int mi = 0; mi < 4; mi++) {
#pragma unroll
        for (int ni = 0; ni < 4; ni++) {
            long col = blkN + wn + ni * 8 + tig * 2;
            float b0 = bias[col], b1 = bias[col + 1];
            long r0 = blkM + wm + mi * 16 + g;
            long r1 = r0 + 8;
            *(float2*)&C[r0 * N + col] = make_float2(acc[mi][ni][0] + b0, acc[mi][ni][1] + b1);
            *(float2*)&C[r1 * N + col] = make_float2(acc[mi][ni][2] + b0, acc[mi][ni][3] + b1);
        }
    }
}

// ---------------------------------------------------------------------------
// Fused LayerNorm + RoPE; emits pre-split, pre-scaled bf16 hi/lo into
// [b][head][s][d] layout. One warp per 128-elem head row.
// ---------------------------------------------------------------------------
__global__ __launch_bounds__(128)
void ln_rope_split_kernel(const float* __restrict__ xbase,
                          const float* __restrict__ g,
                          const float* __restrict__ b,
                          const float* __restrict__ cosp,
                          const float* __restrict__ sinp,
                          int nheads,
                          __nv_bfloat16* __restrict__ oh,
                          __nv_bfloat16* __restrict__ ol,
                          float prescale)
{
    const int warp = threadIdx.x >> 5;
    const int lane = threadIdx.x & 31;
    const long row = (long)blockIdx.x * 4 + warp;
    const long t   = row / nheads;
    const int  h   = (int)(row % nheads);
    const int  bb  = (int)(t >> 10);
    const int  s   = (int)(t & 1023);

    const float* p = xbase + t * NQKV + (long)h * DH;
    float e0 = p[lane], e1 = p[lane + 32], e2 = p[lane + 64], e3 = p[lane + 96];

    float sum = e0 + e1 + e2 + e3;
#pragma unroll
    for (int o = 16; o > 0; o >>= 1) sum += __shfl_xor_sync(0xffffffff, sum, o);
    float mu = sum * (1.0f / DH);

    float d0 = e0 - mu, d1 = e1 - mu, d2 = e2 - mu, d3 = e3 - mu;
    float vs = d0 * d0 + d1 * d1 + d2 * d2 + d3 * d3;
#pragma unroll
    for (int o = 16; o > 0; o >>= 1) vs += __shfl_xor_sync(0xffffffff, vs, o);
    float inv = rsqrtf(vs * (1.0f / DH) + 1e-5f);

    float y0 = d0 * inv * g[lane]      + b[lane];
    float y1 = d1 * inv * g[lane + 32] + b[lane + 32];
    float y2 = d2 * inv * g[lane + 64] + b[lane + 64];
    float y3 = d3 * inv * g[lane + 96] + b[lane + 96];

    const float* cs = cosp + (long)s * DH;
    const float* sn = sinp + (long)s * DH;
    float c0 = cs[lane], c1 = cs[lane + 32], c2 = cs[lane + 64], c3 = cs[lane + 96];
    float s0 = sn[lane], s1 = sn[lane + 32], s2 = sn[lane + 64], s3 = sn[lane + 96];

    float r0 = (y0 * c0 - y2 * s0) * prescale;
    float r1 = (y1 * c1 - y3 * s1) * prescale;
    float r2 = (y2 * c2 + y0 * s2) * prescale;
    float r3 = (y3 * c3 + y1 * s3) * prescale;

    long off = (((long)(bb * nheads + h)) * Sq + s) * DH;
    __nv_bfloat16 h0 = __float2bfloat16(r0), h1 = __float2bfloat16(r1);
    __nv_bfloat16 h2 = __float2bfloat16(r2), h3 = __float2bfloat16(r3);
    oh[off + lane]      = h0;
    oh[off + lane + 32] = h1;
    oh[off + lane + 64] = h2;
    oh[off + lane + 96] = h3;
    ol[off + lane]      = __float2bfloat16(r0 - __bfloat162float(h0));
    ol[off + lane + 32] = __float2bfloat16(r1 - __bfloat162float(h1));
    ol[off + lane + 64] = __float2bfloat16(r2 - __bfloat162float(h2));
    ol[off + lane + 96] = __float2bfloat16(r3 - __bfloat162float(h3));
}

// ---------------------------------------------------------------------------
// Tensor-core causal flash attention, split-bf16 (3-MMA) for QK^T and PV.
// CTA: (b,h,qtile of 128 rows). 8 warps x m16. K-tile = 64 keys, dbl-buffered.
// Output: single fp16 (feeds fp16 O-proj).
// ---------------------------------------------------------------------------
#define FROWB 272
#define FQH 0
#define FQL 34816
#define FKH(buf) (69632  + (buf) * 17408)
#define FKL(buf) (104448 + (buf) * 17408)
#define FVH(buf) (139264 + (buf) * 17408)
#define FVL(buf) (174080 + (buf) * 17408)
#define FSMEM 208896

__global__ __launch_bounds__(256, 1)
void flash_tc_kernel(const __nv_bfloat16* __restrict__ qh,
                     const __nv_bfloat16* __restrict__ ql,
                     const __nv_bfloat16* __restrict__ kh,
                     const __nv_bfloat16* __restrict__ kl,
                     const __nv_bfloat16* __restrict__ vh,
                     const __nv_bfloat16* __restrict__ vl,
                     __half* __restrict__ o16)
{
    extern __shared__ char fsm[];
    const uint32_t sb = (uint32_t)__cvta_generic_to_shared(fsm);

    const int tid  = threadIdx.x;
    const int warp = tid >> 5;
    const int lane = tid & 31;
    const int g    = lane >> 2;
    const int tig  = lane & 3;

    const int bh = blockIdx.x & 31;
    const int qt = 7 - (blockIdx.x >> 5);
    const int b  = bh >> 4;
    const int h  = bh & 15;
    const int khd = h >> 2;

    const __nv_bfloat16* Qhg = qh + (((long)(b * NH + h)) * Sq + (long)qt * 128) * DH;
    const __nv_bfloat16* Qlg = ql + (((long)(b * NH + h)) * Sq + (long)qt * 128) * DH;
    const __nv_bfloat16* Khg = kh + ((long)(b * NHKV + khd)) * Sq * DH;
    const __nv_bfloat16* Klg = kl + ((long)(b * NHKV + khd)) * Sq * DH;
    const __nv_bfloat16* Vhg = vh + ((long)(b * NHKV + khd)) * Sq * DH;
    const __nv_bfloat16* Vlg = vl + ((long)(b * NHKV + khd)) * Sq * DH;

#pragma unroll
    for (int i = 0; i < 8; i++) {
        int idx = tid + i * 256;
        int row = idx >> 4, cg = idx & 15;
        uint32_t doff = (uint32_t)(row * FROWB + cg * 16);
        cp_async16(sb + FQH + doff, Qhg + row * DH + cg * 8);
        cp_async16(sb + FQL + doff, Qlg + row * DH + cg * 8);
    }
    CP_COMMIT();

    {
#pragma unroll
        for (int i = 0; i < 4; i++) {
            int idx = tid + i * 256;
            int row = idx >> 4, cg = idx & 15;
            uint32_t doff = (uint32_t)(row * FROWB + cg * 16);
            long soff = (long)row * DH + cg * 8;
            cp_async16(sb + FKH(0) + doff, Khg + soff);
            cp_async16(sb + FKL(0) + doff, Klg + soff);
            cp_async16(sb + FVH(0) + doff, Vhg + soff);
            cp_async16(sb + FVL(0) + doff, Vlg + soff);
        }
        CP_COMMIT();
    }

    float o[16][4];
#pragma unroll
    for (int nd = 0; nd < 16; nd++)
#pragma unroll
        for (int e = 0; e < 4; e++) o[nd][e] = 0.f;
    float m0 = -1e30f, m1 = -1e30f, l0 = 0.f, l1 = 0.f;

    const int row0 = qt * 128 + warp * 16 + g;
    const int row1 = row0 + 8;

    const uint32_t qhA = sb + FQH + (uint32_t)((warp * 16 + (lane & 15)) * FROWB + (lane >> 4) * 16);
    const uint32_t qlA = qhA + (FQL - FQH);
    const uint32_t kRowOff = (uint32_t)((lane & 7) * FROWB + ((lane >> 3) & 1) * 16);
    const uint32_t vRowOff = (uint32_t)((lane & 15) * FROWB);

    const int nkt = 2 * qt + 2;
    for (int kt = 0; kt < nkt; kt++) {
        const int buf = kt & 1;
        if (kt + 1 < nkt) {
            const int pb = buf ^ 1;
            const long koff = (long)(kt + 1) * 64 * DH;
#pragma unroll
            for (int i = 0; i < 4; i++) {
                int idx = tid + i * 256;
                int row = idx >> 4, cg = idx & 15;
                uint32_t doff = (uint32_t)(row * FROWB + cg * 16);
                long soff = koff + (long)row * DH + cg * 8;
                cp_async16(sb + FKH(pb) + doff, Khg + soff);
                cp_async16(sb + FKL(pb) + doff, Klg + soff);
                cp_async16(sb + FVH(pb) + doff, Vhg + soff);
                cp_async16(sb + FVL(pb) + doff, Vlg + soff);
            }
            CP_COMMIT();
            CP_WAIT1();
        } else {
            CP_WAIT0();
        }
        __syncthreads();

        float s[8][4];
#pragma unroll
        for (int j = 0; j < 8; j++)
#pragma unroll
            for (int e = 0; e < 4; e++) s[j][e] = 0.f;

#pragma unroll
        for (int ks = 0; ks < 8; ks++) {
            uint32_t qh0, qh1, qh2, qh3, ql0, ql1, ql2, ql3;
            LDM_X4(qh0, qh1, qh2, qh3, qhA + ks * 32);
            LDM_X4(ql0, ql1, ql2, ql3, qlA + ks * 32);
            const uint32_t khB = sb + FKH(buf) + kRowOff + ks * 32;
            const uint32_t klB = sb + FKL(buf) + kRowOff + ks * 32;
#pragma unroll
            for (int j = 0; j < 8; j++) {
                uint32_t kb0, kb1, kc0, kc1;
                LDM_X2(kb0, kb1, khB + j * 8 * FROWB);
                LDM_X2(kc0, kc1, klB + j * 8 * FROWB);
                MMA_BF16(s[j], qh0, qh1, qh2, qh3, kb0, kb1);
                MMA_BF16(s[j], qh0, qh1, qh2, qh3, kc0, kc1);
                MMA_BF16(s[j], ql0, ql1, ql2, ql3, kb0, kb1);
            }
        }

        if (kt >= 2 * qt) {
#pragma unroll
            for (int j = 0; j < 8; j++) {
                int c = kt * 64 + j * 8 + 2 * tig;
                if (c     > row0) s[j][0] = -1e30f;
                if (c + 1 > row0) s[j][1] = -1e30f;
                if (c     > row1) s[j][2] = -1e30f;
                if (c + 1 > row1) s[j][3] = -1e30f;
            }
        }

        float rm0 = -1e30f, rm1 = -1e30f;
#pragma unroll
        for (int j = 0; j < 8; j++) {
            rm0 = fmaxf(rm0, fmaxf(s[j][0], s[j][1]));
            rm1 = fmaxf(rm1, fmaxf(s[j][2], s[j][3]));
        }
        rm0 = fmaxf(rm0, __shfl_xor_sync(0xffffffff, rm0, 1));
        rm0 = fmaxf(rm0, __shfl_xor_sync(0xffffffff, rm0, 2));
        rm1 = fmaxf(rm1, __shfl_xor_sync(0xffffffff, rm1, 1));
        rm1 = fmaxf(rm1, __shfl_xor_sync(0xffffffff, rm1, 2));

        float m0n = fmaxf(m0, rm0), m1n = fmaxf(m1, rm1);
        float corr0 = __expf(m0 - m0n), corr1 = __expf(m1 - m1n);
        l0 *= corr0; l1 *= corr1;
#pragma unroll
        for (int nd = 0; nd < 16; nd++) {
            o[nd][0] *= corr0; o[nd][1] *= corr0;
            o[nd][2] *= corr1; o[nd][3] *= corr1;
        }
#pragma unroll
        for (int j = 0; j < 8; j++) {
            s[j][0] = __expf(s[j][0] - m0n);
            s[j][1] = __expf(s[j][1] - m0n);
            s[j][2] = __expf(s[j][2] - m1n);
            s[j][3] = __expf(s[j][3] - m1n);
            l0 += s[j][0] + s[j][1];
            l1 += s[j][2] + s[j][3];
        }
        m0 = m0n; m1 = m1n;

#pragma unroll
        for (int kj = 0; kj < 4; kj++) {
            const int j0 = 2 * kj, j1 = 2 * kj + 1;
            uint32_t ah0 = pack_hi2(s[j0][0], s[j0][1]);
            uint32_t ah1 = pack_hi2(s[j0][2], s[j0][3]);
            uint32_t ah2 = pack_hi2(s[j1][0], s[j1][1]);
            uint32_t ah3 = pack_hi2(s[j1][2], s[j1][3]);
            uint32_t al0 = pack_hi2(bf_res(s[j0][0]), bf_res(s[j0][1]));
            uint32_t al1 = pack_hi2(bf_res(s[j0][2]), bf_res(s[j0][3]));
            uint32_t al2 = pack_hi2(bf_res(s[j1][0]), bf_res(s[j1][1]));
            uint32_t al3 = pack_hi2(bf_res(s[j1][2]), bf_res(s[j1][3]));
            const uint32_t vhB = sb + FVH(buf) + vRowOff + kj * 16 * FROWB;
            const uint32_t vlB = sb + FVL(buf) + vRowOff + kj * 16 * FROWB;
#pragma unroll
            for (int nd = 0; nd < 16; nd++) {
                uint32_t vb0, vb1, vc0, vc1;
                LDM_X2T(vb0, vb1, vhB + nd * 16);
                LDM_X2T(vc0, vc1, vlB + nd * 16);
                MMA_BF16(o[nd], ah0, ah1, ah2, ah3, vb0, vb1);
                MMA_BF16(o[nd], ah0, ah1, ah2, ah3, vc0, vc1);
                MMA_BF16(o[nd], al0, al1, al2, al3, vb0, vb1);
            }
        }
        __syncthreads();
    }

    l0 += __shfl_xor_sync(0xffffffff, l0, 1);
    l0 += __shfl_xor_sync(0xffffffff, l0, 2);
    l1 += __shfl_xor_sync(0xffffffff, l1, 1);
    l1 += __shfl_xor_sync(0xffffffff, l1, 2);
    float inv0 = 1.0f / l0, inv1 = 1.0f / l1;

    const long tok0 = (long)b * Sq + row0;
    long base0 = tok0 * (long)DM + h * DH + 2 * tig;
    long base1 = base0 + 8L * DM;
#pragma unroll
    for (int nd = 0; nd < 16; nd++) {
        float x0 = o[nd][0] * inv0, x1 = o[nd][1] * inv0;
        float x2 = o[nd][2] * inv1, x3 = o[nd][3] * inv1;
        *(uint32_t*)&o16[base0 + nd * 8] = pack_half2f(x0, x1);
        *(uint32_t*)&o16[base1 + nd * 8] = pack_half2f(x2, x3);
    }
}

// ---------------------------------------------------------------------------
extern "C" void kernel_launch(void* const* d_in, const int* in_sizes, int n_in,
                              void* d_out, int out_size)
{
    const float* hidden = (const float*)d_in[0];
    const float* cosp   = (const float*)d_in[1];
    const float* sinp   = (const float*)d_in[2];
    const float* Wq     = (const float*)d_in[3];
    const float* bq     = (const float*)d_in[4];
    const float* Wk     = (const float*)d_in[5];
    const float* bk     = (const float*)d_in[6];
    const float* Wv     = (const float*)d_in[7];
    const float* bv     = (const float*)d_in[8];
    const float* Wo     = (const float*)d_in[9];
    const float* bo     = (const float*)d_in[10];
    const float* qn_g   = (const float*)d_in[11];
    const float* qn_b   = (const float*)d_in[12];
    const float* kn_g   = (const float*)d_in[13];
    const float* kn_b   = (const float*)d_in[14];
    float* out = (float*)d_out;

    __half *hid16, *wqkv16, *wo16, *ao16;
    __nv_bfloat16 *qhb, *qlb, *khb, *klb, *vhb, *vlb;
    float *biasq, *qkv;
    cudaGetSymbolAddress((void**)&hid16,  g_hid16);
    cudaGetSymbolAddress((void**)&wqkv16, g_wqkv16);
    cudaGetSymbolAddress((void**)&wo16,   g_wo16);
    cudaGetSymbolAddress((void**)&ao16,   g_ao16);
    cudaGetSymbolAddress((void**)&biasq,  g_bias);
    cudaGetSymbolAddress((void**)&qkv,    g_qkv);
    cudaGetSymbolAddress((void**)&qhb,    g_qh);
    cudaGetSymbolAddress((void**)&qlb,    g_ql);
    cudaGetSymbolAddress((void**)&khb,    g_kh);
    cudaGetSymbolAddress((void**)&klb,    g_kl);
    cudaGetSymbolAddress((void**)&vhb,    g_vh);
    cudaGetSymbolAddress((void**)&vlb,    g_vl);

    cudaFuncSetAttribute(gemm_f16_kernel,
                         cudaFuncAttributeMaxDynamicSharedMemorySize, 2 * STAGE16_B);
    cudaFuncSetAttribute(flash_tc_kernel,
                         cudaFuncAttributeMaxDynamicSharedMemorySize, FSMEM);

    // ---- fp32 -> fp16 conversions ----
    {
        int n4;
        n4 = TOKENS * DM / 4;
        to_half_kernel<<<(n4 + 255) / 256, 256>>>(hidden, hid16, n4);
        n4 = 2048 * DM / 4;
        to_half_kernel<<<(n4 + 255) / 256, 256>>>(Wq, wqkv16, n4);
        n4 = 512 * DM / 4;
        to_half_kernel<<<(n4 + 255) / 256, 256>>>(Wk, wqkv16 + 2048L * DM, n4);
        to_half_kernel<<<(n4 + 255) / 256, 256>>>(Wv, wqkv16 + 2560L * DM, n4);
        n4 = DM * DM / 4;
        to_half_kernel<<<(n4 + 255) / 256, 256>>>(Wo, wo16, n4);
        concat_bias_kernel<<<12, 256>>>(bq, bk, bv, biasq);
    }

    // ---- fused QKV projection (fp16 single-pass) ----
    {
        dim3 grid(NQKV / 128, TOKENS / 128);
        gemm_f16_kernel<<<grid, 256, 2 * STAGE16_B>>>(hid16, wqkv16, biasq, qkv,
                                                      TOKENS, NQKV, DM);
    }

    // ---- LN + RoPE -> pre-split bf16 (q pre-scaled by 1/sqrt(Dh)) ----
    const float scale = 0.08838834764831845f;
    ln_rope_split_kernel<<<TOKENS * NH   / 4, 128>>>(qkv,        qn_g, qn_b, cosp, sinp,
                                                     NH,   qhb, qlb, scale);
    ln_rope_split_kernel<<<TOKENS * NHKV / 4, 128>>>(qkv + KOFF, kn_g, kn_b, cosp, sinp,
                                                     NHKV, khb, klb, 1.0f);
    vsplit_kernel<<<TOKENS * NHKV * DH / 4 / 256, 256>>>(qkv, vhb, vlb);

    // ---- tensor-core causal flash attention (split-bf16 kept) ----
    flash_tc_kernel<<<256, 256, FSMEM>>>(qhb, qlb, khb, klb, vhb, vlb, ao16);

    // ---- output projection (fp16 single-pass) ----
    {
        dim3 grid(DM / 128, TOKENS / 128);
        gemm_f16_kernel<<<grid, 256, 2 * STAGE16_B>>>(ao16, wo16, bo, out,
                                                      TOKENS, DM, DM);
    }
}

// round 8
// speedup vs baseline: 9.3870x; 1.1153x over previous
#include <cuda_runtime.h>
#include <cuda_bf16.h>
#include <cuda_fp16.h>
#include <math.h>
#include <stdint.h>

// Problem constants (fixed by setup_inputs)
#define Bq   2
#define Sq   1024
#define DM   2048
#define NH   16
#define NHKV 4
#define DH   128
#define TOKENS (Bq * Sq)          // 2048
#define NREP (NH / NHKV)          // 4
#define NQKV 3072                 // fused QKV output width
#define KOFF 2048
#define VOFF 2560

// ---------------------------------------------------------------------------
// Scratch (__device__ globals; no allocation allowed)
// ---------------------------------------------------------------------------
__device__ __align__(16) __half g_hid16 [TOKENS * DM];
__device__ __align__(16) __half g_wqkv16[NQKV   * DM];
__device__ __align__(16) __half g_wo16  [DM     * DM];
__device__ float               g_bias   [NQKV];
__device__ __align__(16) float g_qkv    [TOKENS * NQKV];
// fp16 attention operands, [b][head][s][d]
__device__ __align__(16) __half g_q16[TOKENS * NH   * DH];
__device__ __align__(16) __half g_k16[TOKENS * NHKV * DH];
__device__ __align__(16) __half g_v16[TOKENS * NHKV * DH];
__device__ __align__(16) __half g_ao16[TOKENS * DM];

// ---------------------------------------------------------------------------
// helpers
// ---------------------------------------------------------------------------
__device__ __forceinline__ uint32_t pack_half2f(float x, float y) {
    __half2 h = __floats2half2_rn(x, y);
    return *(uint32_t*)&h;
}

#define LDM_X4(r0,r1,r2,r3,addr) \
    asm volatile("ldmatrix.sync.aligned.m8n8.x4.shared.b16 {%0,%1,%2,%3}, [%4];" \
                 : "=r"(r0),"=r"(r1),"=r"(r2),"=r"(r3) : "r"(addr))
#define LDM_X2(r0,r1,addr) \
    asm volatile("ldmatrix.sync.aligned.m8n8.x2.shared.b16 {%0,%1}, [%2];" \
                 : "=r"(r0),"=r"(r1) : "r"(addr))
#define LDM_X2T(r0,r1,addr) \
    asm volatile("ldmatrix.sync.aligned.m8n8.x2.trans.shared.b16 {%0,%1}, [%2];" \
                 : "=r"(r0),"=r"(r1) : "r"(addr))
#define MMA_F16(c,a0,a1,a2,a3,b0,b1) \
    asm volatile("mma.sync.aligned.m16n8k16.row.col.f32.f16.f16.f32 " \
                 "{%0,%1,%2,%3},{%4,%5,%6,%7},{%8,%9},{%0,%1,%2,%3};" \
                 : "+f"(c[0]),"+f"(c[1]),"+f"(c[2]),"+f"(c[3]) \
                 : "r"(a0),"r"(a1),"r"(a2),"r"(a3),"r"(b0),"r"(b1))

__device__ __forceinline__ void cp_async16(uint32_t dst, const void* src) {
    asm volatile("cp.async.cg.shared.global [%0], [%1], 16;" :: "r"(dst), "l"(src));
}
#define CP_COMMIT() asm volatile("cp.async.commit_group;")
#define CP_WAIT1()  asm volatile("cp.async.wait_group 1;")
#define CP_WAIT0()  asm volatile("cp.async.wait_group 0;")

// ---------------------------------------------------------------------------
// convert: fp32 -> fp16
// ---------------------------------------------------------------------------
__global__ __launch_bounds__(256)
void to_half_kernel(const float* __restrict__ src,
                    __half* __restrict__ dst, int n4)
{
    int i = blockIdx.x * 256 + threadIdx.x;
    if (i >= n4) return;
    float4 t = ((const float4*)src)[i];
    uint2 h;
    h.x = pack_half2f(t.x, t.y);
    h.y = pack_half2f(t.z, t.w);
    ((uint2*)dst)[i] = h;
}

__global__ void concat_bias_kernel(const float* bq, const float* bk,
                                   const float* bv, float* dst)
{
    int i = blockIdx.x * 256 + threadIdx.x;
    if (i < 2048)      dst[i] = bq[i];
    else if (i < 2560) dst[i] = bk[i - 2048];
    else if (i < 3072) dst[i] = bv[i - 2560];
}

// V convert + layout permute: g_qkv v-section -> [b][kh][s][d] fp16
__global__ __launch_bounds__(256)
void vconv_kernel(const float* __restrict__ qkv,
                  __half* __restrict__ v16)
{
    int idx = blockIdx.x * 256 + threadIdx.x;
    int vi = idx * 4;
    int t = vi >> 9;
    int c = vi & 511;
    int kh = c >> 7;
    int d  = c & 127;
    int b = t >> 10, s = t & 1023;
    float4 val = *(const float4*)&qkv[(long)t * NQKV + VOFF + c];
    long o = (((long)(b * NHKV + kh)) * Sq + s) * DH + d;
    uint2 h;
    h.x = pack_half2f(val.x, val.y);
    h.y = pack_half2f(val.z, val.w);
    *(uint2*)&v16[o] = h;
}

// ---------------------------------------------------------------------------
// Single-pass fp16 tensor-core GEMM, cp.async double-buffered. (verified)
// ---------------------------------------------------------------------------
#define BKP 40
#define TILE16_B (128 * BKP * 2)
#define STAGE16_B (2 * TILE16_B)

__global__ __launch_bounds__(256)
void gemm_f16_kernel(const __half* __restrict__ Ag,
                     const __half* __restrict__ Bg,
                     const float* __restrict__ bias,
                     float* __restrict__ C,
                     int M, int N, int K)
{
    extern __shared__ __half sm16[];
    const uint32_t smBase = (uint32_t)__cvta_generic_to_shared(sm16);

    const int tid  = threadIdx.x;
    const int warp = tid >> 5;
    const int lane = tid & 31;
    const int wm   = (warp >> 2) * 64;
    const int wn   = (warp & 3) * 32;
    const int g    = lane >> 2;
    const int tig  = lane & 3;
    const long blkM = (long)blockIdx.y * 128;
    const long blkN = (long)blockIdx.x * 128;

    float acc[4][4][4];
#pragma unroll
    for (int mi = 0; mi < 4; mi++)
#pragma unroll
        for (int ni = 0; ni < 4; ni++)
#pragma unroll
            for (int e = 0; e < 4; e++) acc[mi][ni][e] = 0.f;

    const int aRow = wm + (lane & 15);
    const int aCol = (lane >> 4) * 8;
    const int bRow = wn + (lane & 7);
    const int bCol = ((lane >> 3) & 1) * 8;

    const int KT = K / 32;

    {
        uint32_t st = smBase;
#pragma unroll
        for (int i = 0; i < 2; i++) {
            int c = tid + i * 256;
            int row = c >> 2, col = (c & 3) * 8;
            uint32_t d = st + (uint32_t)(row * BKP + col) * 2;
            cp_async16(d,            Ag + (blkM + row) * (long)K + col);
            cp_async16(d + TILE16_B, Bg + (blkN + row) * (long)K + col);
        }
        CP_COMMIT();
    }

    for (int kt = 0; kt < KT; kt++) {
        if (kt + 1 < KT) {
            uint32_t st = smBase + ((kt + 1) & 1) * STAGE16_B;
            int k0 = (kt + 1) * 32;
#pragma unroll
            for (int i = 0; i < 2; i++) {
                int c = tid + i * 256;
                int row = c >> 2, col = (c & 3) * 8;
                uint32_t d = st + (uint32_t)(row * BKP + col) * 2;
                cp_async16(d,            Ag + (blkM + row) * (long)K + k0 + col);
                cp_async16(d + TILE16_B, Bg + (blkN + row) * (long)K + k0 + col);
            }
            CP_COMMIT();
            CP_WAIT1();
        } else {
            CP_WAIT0();
        }
        __syncthreads();

        const uint32_t st = smBase + (kt & 1) * STAGE16_B;
#pragma unroll
        for (int kk = 0; kk < 32; kk += 16) {
            uint32_t a[4][4], b[4][2];
#pragma unroll
            for (int mi = 0; mi < 4; mi++) {
                uint32_t off = (uint32_t)(((aRow + mi * 16) * BKP + kk + aCol) * 2);
                LDM_X4(a[mi][0], a[mi][1], a[mi][2], a[mi][3], st + off);
            }
#pragma unroll
            for (int ni = 0; ni < 4; ni++) {
                uint32_t off = (uint32_t)(((bRow + ni * 8) * BKP + kk + bCol) * 2);
                LDM_X2(b[ni][0], b[ni][1], st + TILE16_B + off);
            }
#pragma unroll
            for (int mi = 0; mi < 4; mi++)
#pragma unroll
                for (int ni = 0; ni < 4; ni++)
                    MMA_F16(acc[mi][ni], a[mi][0], a[mi][1], a[mi][2], a[mi][3],
                            b[ni][0], b[ni][1]);
        }
        __syncthreads();
    }

#pragma unroll
    for (int mi = 0; mi < 4; mi++) {
#pragma unroll
        for (int ni = 0; ni < 4; ni++) {
            long col = blkN + wn + ni * 8 + tig * 2;
            float b0 = bias[col], b1 = bias[col + 1];
            long r0 = blkM + wm + mi * 16 + g;
            long r1 = r0 + 8;
            *(float2*)&C[r0 * N + col] = make_float2(acc[mi][ni][0] + b0, acc[mi][ni][1] + b1);
            *(float2*)&C[r1 * N + col] = make_float2(acc[mi][ni][2] + b0, acc[mi][ni][3] + b1);
        }
    }
}

// ---------------------------------------------------------------------------
// Fused LayerNorm + RoPE; emits fp16 into [b][head][s][d]. One warp per row.
// ---------------------------------------------------------------------------
__global__ __launch_bounds__(128)
void ln_rope_f16_kernel(const float* __restrict__ xbase,
                        const float* __restrict__ g,
                        const float* __restrict__ b,
                        const float* __restrict__ cosp,
                        const float* __restrict__ sinp,
                        int nheads,
                        __half* __restrict__ o16,
                        float prescale)
{
    const int warp = threadIdx.x >> 5;
    const int lane = threadIdx.x & 31;
    const long row = (long)blockIdx.x * 4 + warp;
    const long t   = row / nheads;
    const int  h   = (int)(row % nheads);
    const int  bb  = (int)(t >> 10);
    const int  s   = (int)(t & 1023);

    const float* p = xbase + t * NQKV + (long)h * DH;
    float e0 = p[lane], e1 = p[lane + 32], e2 = p[lane + 64], e3 = p[lane + 96];

    float sum = e0 + e1 + e2 + e3;
#pragma unroll
    for (int o = 16; o > 0; o >>= 1) sum += __shfl_xor_sync(0xffffffff, sum, o);
    float mu = sum * (1.0f / DH);

    float d0 = e0 - mu, d1 = e1 - mu, d2 = e2 - mu, d3 = e3 - mu;
    float vs = d0 * d0 + d1 * d1 + d2 * d2 + d3 * d3;
#pragma unroll
    for (int o = 16; o > 0; o >>= 1) vs += __shfl_xor_sync(0xffffffff, vs, o);
    float inv = rsqrtf(vs * (1.0f / DH) + 1e-5f);

    float y0 = d0 * inv * g[lane]      + b[lane];
    float y1 = d1 * inv * g[lane + 32] + b[lane + 32];
    float y2 = d2 * inv * g[lane + 64] + b[lane + 64];
    float y3 = d3 * inv * g[lane + 96] + b[lane + 96];

    const float* cs = cosp + (long)s * DH;
    const float* sn = sinp + (long)s * DH;
    float c0 = cs[lane], c1 = cs[lane + 32], c2 = cs[lane + 64], c3 = cs[lane + 96];
    float s0 = sn[lane], s1 = sn[lane + 32], s2 = sn[lane + 64], s3 = sn[lane + 96];

    float r0 = (y0 * c0 - y2 * s0) * prescale;
    float r1 = (y1 * c1 - y3 * s1) * prescale;
    float r2 = (y2 * c2 + y0 * s2) * prescale;
    float r3 = (y3 * c3 + y1 * s3) * prescale;

    long off = (((long)(bb * nheads + h)) * Sq + s) * DH;
    o16[off + lane]      = __float2half_rn(r0);
    o16[off + lane + 32] = __float2half_rn(r1);
    o16[off + lane + 64] = __float2half_rn(r2);
    o16[off + lane + 96] = __float2half_rn(r3);
}

// ---------------------------------------------------------------------------
// Tensor-core causal flash attention, single-pass fp16.
// CTA: (b,h,qtile of 128 rows). 8 warps x m16. K-tile = 64 keys, dbl-buffered.
// ---------------------------------------------------------------------------
#define FROWB 272                      // padded row stride bytes (136 halfs)
#define FQ 0                           // 128 x FROWB = 34816
#define FK(buf) (34816 + (buf) * 17408)
#define FV(buf) (69632 + (buf) * 17408)
#define FSMEM 104448

__global__ __launch_bounds__(256)
void flash_tc_kernel(const __half* __restrict__ q16,
                     const __half* __restrict__ k16,
                     const __half* __restrict__ v16,
                     __half* __restrict__ o16)
{
    extern __shared__ char fsm[];
    const uint32_t sb = (uint32_t)__cvta_generic_to_shared(fsm);

    const int tid  = threadIdx.x;
    const int warp = tid >> 5;
    const int lane = tid & 31;
    const int g    = lane >> 2;
    const int tig  = lane & 3;

    const int bh = blockIdx.x & 31;
    const int qt = 7 - (blockIdx.x >> 5);      // heavy tiles first
    const int b  = bh >> 4;
    const int h  = bh & 15;
    const int khd = h >> 2;

    const __half* Qg = q16 + (((long)(b * NH + h)) * Sq + (long)qt * 128) * DH;
    const __half* Kg = k16 + ((long)(b * NHKV + khd)) * Sq * DH;
    const __half* Vg = v16 + ((long)(b * NHKV + khd)) * Sq * DH;

    // Q tile: 128 rows x 16 chunks of 16B
#pragma unroll
    for (int i = 0; i < 8; i++) {
        int idx = tid + i * 256;
        int row = idx >> 4, cg = idx & 15;
        cp_async16(sb + FQ + (uint32_t)(row * FROWB + cg * 16),
                   Qg + row * DH + cg * 8);
    }
    CP_COMMIT();

    // KV tile 0: 64 rows x 16 chunks each
    {
#pragma unroll
        for (int i = 0; i < 4; i++) {
            int idx = tid + i * 256;
            int row = idx >> 4, cg = idx & 15;
            uint32_t doff = (uint32_t)(row * FROWB + cg * 16);
            long soff = (long)row * DH + cg * 8;
            cp_async16(sb + FK(0) + doff, Kg + soff);
            cp_async16(sb + FV(0) + doff, Vg + soff);
        }
        CP_COMMIT();
    }

    float o[16][4];
#pragma unroll
    for (int nd = 0; nd < 16; nd++)
#pragma unroll
        for (int e = 0; e < 4; e++) o[nd][e] = 0.f;
    float m0 = -1e30f, m1 = -1e30f, l0 = 0.f, l1 = 0.f;

    const int row0 = qt * 128 + warp * 16 + g;
    const int row1 = row0 + 8;

    const uint32_t qA = sb + FQ + (uint32_t)((warp * 16 + (lane & 15)) * FROWB + (lane >> 4) * 16);
    const uint32_t kRowOff = (uint32_t)((lane & 7) * FROWB + ((lane >> 3) & 1) * 16);
    const uint32_t vRowOff = (uint32_t)((lane & 15) * FROWB);

    const int nkt = 2 * qt + 2;
    for (int kt = 0; kt < nkt; kt++) {
        const int buf = kt & 1;
        if (kt + 1 < nkt) {
            const int pb = buf ^ 1;
            const long koff = (long)(kt + 1) * 64 * DH;
#pragma unroll
            for (int i = 0; i < 4; i++) {
                int idx = tid + i * 256;
                int row = idx >> 4, cg = idx & 15;
                uint32_t doff = (uint32_t)(row * FROWB + cg * 16);
                long soff = koff + (long)row * DH + cg * 8;
                cp_async16(sb + FK(pb) + doff, Kg + soff);
                cp_async16(sb + FV(pb) + doff, Vg + soff);
            }
            CP_COMMIT();
            CP_WAIT1();
        } else {
            CP_WAIT0();
        }
        __syncthreads();

        // ---- S = Q K^T, single-pass fp16 ----
        float s[8][4];
#pragma unroll
        for (int j = 0; j < 8; j++)
#pragma unroll
            for (int e = 0; e < 4; e++) s[j][e] = 0.f;

#pragma unroll
        for (int ks = 0; ks < 8; ks++) {
            uint32_t q0, q1, q2, q3;
            LDM_X4(q0, q1, q2, q3, qA + ks * 32);
            const uint32_t kB = sb + FK(buf) + kRowOff + ks * 32;
#pragma unroll
            for (int j = 0; j < 8; j++) {
                uint32_t kb0, kb1;
                LDM_X2(kb0, kb1, kB + j * 8 * FROWB);
                MMA_F16(s[j], q0, q1, q2, q3, kb0, kb1);
            }
        }

        // ---- causal mask ----
        if (kt >= 2 * qt) {
#pragma unroll
            for (int j = 0; j < 8; j++) {
                int c = kt * 64 + j * 8 + 2 * tig;
                if (c     > row0) s[j][0] = -1e30f;
                if (c + 1 > row0) s[j][1] = -1e30f;
                if (c     > row1) s[j][2] = -1e30f;
                if (c + 1 > row1) s[j][3] = -1e30f;
            }
        }

        // ---- online softmax ----
        float rm0 = -1e30f, rm1 = -1e30f;
#pragma unroll
        for (int j = 0; j < 8; j++) {
            rm0 = fmaxf(rm0, fmaxf(s[j][0], s[j][1]));
            rm1 = fmaxf(rm1, fmaxf(s[j][2], s[j][3]));
        }
        rm0 = fmaxf(rm0, __shfl_xor_sync(0xffffffff, rm0, 1));
        rm0 = fmaxf(rm0, __shfl_xor_sync(0xffffffff, rm0, 2));
        rm1 = fmaxf(rm1, __shfl_xor_sync(0xffffffff, rm1, 1));
        rm1 = fmaxf(rm1, __shfl_xor_sync(0xffffffff, rm1, 2));

        float m0n = fmaxf(m0, rm0), m1n = fmaxf(m1, rm1);
        float corr0 = __expf(m0 - m0n), corr1 = __expf(m1 - m1n);
        l0 *= corr0; l1 *= corr1;
#pragma unroll
        for (int nd = 0; nd < 16; nd++) {
            o[nd][0] *= corr0; o[nd][1] *= corr0;
            o[nd][2] *= corr1; o[nd][3] *= corr1;
        }
#pragma unroll
        for (int j = 0; j < 8; j++) {
            s[j][0] = __expf(s[j][0] - m0n);
            s[j][1] = __expf(s[j][1] - m0n);
            s[j][2] = __expf(s[j][2] - m1n);
            s[j][3] = __expf(s[j][3] - m1n);
            l0 += s[j][0] + s[j][1];
            l1 += s[j][2] + s[j][3];
        }
        m0 = m0n; m1 = m1n;

        // ---- O += P V, single-pass fp16 ----
#pragma unroll
        for (int kj = 0; kj < 4; kj++) {
            const int j0 = 2 * kj, j1 = 2 * kj + 1;
            uint32_t a0 = pack_half2f(s[j0][0], s[j0][1]);
            uint32_t a1 = pack_half2f(s[j0][2], s[j0][3]);
            uint32_t a2 = pack_half2f(s[j1][0], s[j1][1]);
            uint32_t a3 = pack_half2f(s[j1][2], s[j1][3]);
            const uint32_t vB = sb + FV(buf) + vRowOff + kj * 16 * FROWB;
#pragma unroll
            for (int nd = 0; nd < 16; nd++) {
                uint32_t vb0, vb1;
                LDM_X2T(vb0, vb1, vB + nd * 16);
                MMA_F16(o[nd], a0, a1, a2, a3, vb0, vb1);
            }
        }
        __syncthreads();
    }

    l0 += __shfl_xor_sync(0xffffffff, l0, 1);
    l0 += __shfl_xor_sync(0xffffffff, l0, 2);
    l1 += __shfl_xor_sync(0xffffffff, l1, 1);
    l1 += __shfl_xor_sync(0xffffffff, l1, 2);
    float inv0 = 1.0f / l0, inv1 = 1.0f / l1;

    const long tok0 = (long)b * Sq + row0;
    long base0 = tok0 * (long)DM + h * DH + 2 * tig;
    long base1 = base0 + 8L * DM;
#pragma unroll
    for (int nd = 0; nd < 16; nd++) {
        *(uint32_t*)&o16[base0 + nd * 8] = pack_half2f(o[nd][0] * inv0, o[nd][1] * inv0);
        *(uint32_t*)&o16[base1 + nd * 8] = pack_half2f(o[nd][2] * inv1, o[nd][3] * inv1);
    }
}

// ---------------------------------------------------------------------------
extern "C" void kernel_launch(void* const* d_in, const int* in_sizes, int n_in,
                              void* d_out, int out_size)
{
    const float* hidden = (const float*)d_in[0];
    const float* cosp   = (const float*)d_in[1];
    const float* sinp   = (const float*)d_in[2];
    const float* Wq     = (const float*)d_in[3];
    const float* bq     = (const float*)d_in[4];
    const float* Wk     = (const float*)d_in[5];
    const float* bk     = (const float*)d_in[6];
    const float* Wv     = (const float*)d_in[7];
    const float* bv     = (const float*)d_in[8];
    const float* Wo     = (const float*)d_in[9];
    const float* bo     = (const float*)d_in[10];
    const float* qn_g   = (const float*)d_in[11];
    const float* qn_b   = (const float*)d_in[12];
    const float* kn_g   = (const float*)d_in[13];
    const float* kn_b   = (const float*)d_in[14];
    float* out = (float*)d_out;

    __half *hid16, *wqkv16, *wo16, *ao16, *q16, *k16, *v16;
    float *biasq, *qkv;
    cudaGetSymbolAddress((void**)&hid16,  g_hid16);
    cudaGetSymbolAddress((void**)&wqkv16, g_wqkv16);
    cudaGetSymbolAddress((void**)&wo16,   g_wo16);
    cudaGetSymbolAddress((void**)&ao16,   g_ao16);
    cudaGetSymbolAddress((void**)&biasq,  g_bias);
    cudaGetSymbolAddress((void**)&qkv,    g_qkv);
    cudaGetSymbolAddress((void**)&q16,    g_q16);
    cudaGetSymbolAddress((void**)&k16,    g_k16);
    cudaGetSymbolAddress((void**)&v16,    g_v16);

    cudaFuncSetAttribute(gemm_f16_kernel,
                         cudaFuncAttributeMaxDynamicSharedMemorySize, 2 * STAGE16_B);
    cudaFuncSetAttribute(flash_tc_kernel,
                         cudaFuncAttributeMaxDynamicSharedMemorySize, FSMEM);

    // ---- fp32 -> fp16 conversions ----
    {
        int n4;
        n4 = TOKENS * DM / 4;
        to_half_kernel<<<(n4 + 255) / 256, 256>>>(hidden, hid16, n4);
        n4 = 2048 * DM / 4;
        to_half_kernel<<<(n4 + 255) / 256, 256>>>(Wq, wqkv16, n4);
        n4 = 512 * DM / 4;
        to_half_kernel<<<(n4 + 255) / 256, 256>>>(Wk, wqkv16 + 2048L * DM, n4);
        to_half_kernel<<<(n4 + 255) / 256, 256>>>(Wv, wqkv16 + 2560L * DM, n4);
        n4 = DM * DM / 4;
        to_half_kernel<<<(n4 + 255) / 256, 256>>>(Wo, wo16, n4);
        concat_bias_kernel<<<12, 256>>>(bq, bk, bv, biasq);
    }

    // ---- fused QKV projection ----
    {
        dim3 grid(NQKV / 128, TOKENS / 128);
        gemm_f16_kernel<<<grid, 256, 2 * STAGE16_B>>>(hid16, wqkv16, biasq, qkv,
                                                      TOKENS, NQKV, DM);
    }

    // ---- LN + RoPE -> fp16 (q pre-scaled by 1/sqrt(Dh)) ----
    const float scale = 0.08838834764831845f;
    ln_rope_f16_kernel<<<TOKENS * NH   / 4, 128>>>(qkv,        qn_g, qn_b, cosp, sinp,
                                                   NH,   q16, scale);
    ln_rope_f16_kernel<<<TOKENS * NHKV / 4, 128>>>(qkv + KOFF, kn_g, kn_b, cosp, sinp,
                                                   NHKV, k16, 1.0f);
    vconv_kernel<<<TOKENS * NHKV * DH / 4 / 256, 256>>>(qkv, v16);

    // ---- tensor-core causal flash attention (fp16 single-pass) ----
    flash_tc_kernel<<<256, 256, FSMEM>>>(q16, k16, v16, ao16);

    // ---- output projection ----
    {
        dim3 grid(DM / 128, TOKENS / 128);
        gemm_f16_kernel<<<grid, 256, 2 * STAGE16_B>>>(ao16, wo16, bo, out,
                                                      TOKENS, DM, DM);
    }
}